// round 9
// baseline (speedup 1.0000x reference)
#include <cuda_runtime.h>
#include <cuda_fp16.h>
#include <cstdint>

// Problem constants (fixed shapes)
#define BZ 4
#define TN 4096
#define DN 1024
#define MN (BZ*TN)        // 16384 rows
#define SEG 64
#define NSEG (TN/SEG)     // 64

// ---------------------------------------------------------------------------
// Scratch (static __device__ arrays; no allocation allowed)
// ---------------------------------------------------------------------------
__device__ __half g_xnorm[(size_t)MN*DN];   // fp16 LN output
__device__ __half g_la   [(size_t)MN*DN];   // fp16 log_alpha
__device__ __half g_bx   [(size_t)MN*DN];   // fp16 beta_x
__device__ float  g_scan [(size_t)MN*DN];   // f32 scan output
__device__ __half g_scanh[(size_t)MN*DN];   // fp16 row-scaled scan output
__device__ float  g_rmax [MN];              // per-row scale
__device__ __half g_wf   [(size_t)DN*DN];   // fp16 Wf
__device__ __half g_wrh  [(size_t)DN*DN];   // fp16 Wr
__device__ float  g_segL[BZ*NSEG*DN];
__device__ float  g_segP[BZ*NSEG*DN];
__device__ float  g_Lb  [BZ*NSEG*DN];
__device__ float  g_sb  [BZ*NSEG*DN];

// ---------------------------------------------------------------------------
// Helpers
// ---------------------------------------------------------------------------
__device__ __forceinline__ void cp16(void* smem, const void* g) {
    uint32_t s = (uint32_t)__cvta_generic_to_shared(smem);
    asm volatile("cp.async.cg.shared.global [%0], [%1], 16;\n" :: "r"(s), "l"(g));
}
__device__ __forceinline__ void cp_commit() {
    asm volatile("cp.async.commit_group;\n");
}
__device__ __forceinline__ void ldsm4(uint32_t& r0, uint32_t& r1, uint32_t& r2,
                                      uint32_t& r3, uint32_t addr) {
    asm volatile("ldmatrix.sync.aligned.m8n8.x4.shared.b16 {%0,%1,%2,%3}, [%4];\n"
                 : "=r"(r0), "=r"(r1), "=r"(r2), "=r"(r3) : "r"(addr));
}
__device__ __forceinline__ void mma_f16(float* c, const uint32_t* a, const uint32_t* b) {
    asm volatile(
        "mma.sync.aligned.m16n8k16.row.col.f32.f16.f16.f32 "
        "{%0,%1,%2,%3}, {%4,%5,%6,%7}, {%8,%9}, {%0,%1,%2,%3};\n"
        : "+f"(c[0]), "+f"(c[1]), "+f"(c[2]), "+f"(c[3])
        : "r"(a[0]), "r"(a[1]), "r"(a[2]), "r"(a[3]),
          "r"(b[0]), "r"(b[1]));
}

// ---------------------------------------------------------------------------
// Kernel 0: convert f32 weight matrix to fp16
// ---------------------------------------------------------------------------
__global__ __launch_bounds__(256) void cvt_h_kernel(
    const float* __restrict__ in, __half* __restrict__ out)
{
    const int i = blockIdx.x * 256 + threadIdx.x;
    const float4 v = ((const float4*)in)[i];
    __half2 h01 = __floats2half2_rn(v.x, v.y);
    __half2 h23 = __floats2half2_rn(v.z, v.w);
    uint2 pk;
    pk.x = *(uint32_t*)&h01;
    pk.y = *(uint32_t*)&h23;
    *(uint2*)(out + (size_t)i * 4) = pk;
}

// ---------------------------------------------------------------------------
// Kernel 1: LayerNorm, one WARP per row, fp16 output.
// ---------------------------------------------------------------------------
__global__ __launch_bounds__(256) void ln_kernel(
    const float* __restrict__ x, const float* __restrict__ w,
    const float* __restrict__ b, __half* __restrict__ y)
{
    const int warp = threadIdx.x >> 5;
    const int lane = threadIdx.x & 31;
    const int row  = blockIdx.x * 8 + warp;

    const float4* xr = (const float4*)(x + (size_t)row * DN);

    float s = 0.f;
    #pragma unroll
    for (int i = 0; i < 8; i++) {
        const float4 v = xr[lane + 32*i];
        s += (v.x + v.y) + (v.z + v.w);
    }
    #pragma unroll
    for (int o = 16; o > 0; o >>= 1) s += __shfl_xor_sync(0xffffffffu, s, o);
    const float mu = s * (1.0f / DN);

    float s2 = 0.f;
    #pragma unroll
    for (int i = 0; i < 8; i++) {
        const float4 v = xr[lane + 32*i];
        const float d0 = v.x - mu, d1 = v.y - mu, d2 = v.z - mu, d3 = v.w - mu;
        s2 += (d0*d0 + d1*d1) + (d2*d2 + d3*d3);
    }
    #pragma unroll
    for (int o = 16; o > 0; o >>= 1) s2 += __shfl_xor_sync(0xffffffffu, s2, o);
    const float rs = rsqrtf(s2 * (1.0f / DN) + 1e-5f);

    const float4* wv = (const float4*)w;
    const float4* bv = (const float4*)b;
    #pragma unroll
    for (int i = 0; i < 8; i++) {
        const int c = lane + 32*i;
        const float4 v  = xr[c];
        const float4 w4 = wv[c];
        const float4 b4 = bv[c];
        __half2 h01 = __floats2half2_rn((v.x - mu) * rs * w4.x + b4.x,
                                        (v.y - mu) * rs * w4.y + b4.y);
        __half2 h23 = __floats2half2_rn((v.z - mu) * rs * w4.z + b4.z,
                                        (v.w - mu) * rs * w4.w + b4.w);
        uint2 pk;
        pk.x = *(uint32_t*)&h01;
        pk.y = *(uint32_t*)&h23;
        *(uint2*)(y + (size_t)row * DN + c*4) = pk;
    }
}

// ---------------------------------------------------------------------------
// fp16 GEMM (shared body): C[m,n] = sum_k A[m,k]*W[n,k], fp16 in, f32 accum.
// 128x128 tile, BK=64 per stage (KT=16 -> 16 barriers), 3-stage cp.async,
// ldmatrix fragments with register double-buffering, 2 CTAs/SM.
// EPI==1: sigmoid/log_alpha/beta_x epilogue (fp16 out).
// EPI==2: per-row-rescale + tanh*0.05 + residual (f32 out).
// ---------------------------------------------------------------------------
#define RSH 72                        // smem row stride in halves (144B)
#define STAGE_H (128*RSH)             // halves per operand per stage (9216)
#define STG_BYTES (2*STAGE_H*2)       // A+B bytes per stage = 36864
#define NST 3
#define GEMMH_SMEM (NST*STG_BYTES)    // 110592 (2 CTAs/SM: 2x110592 < 228KB)

template<int EPI>
__global__ __launch_bounds__(256, 2) void gemm_h(
    const __half* __restrict__ A, const __half* __restrict__ W,
    const float* __restrict__ bias,
    const float* __restrict__ sc1,    // alpha_bias (EPI==1)
    const float* __restrict__ sc2,    // beta_scale (EPI==1)
    const __half* __restrict__ XrefH, // x_norm fp16 (EPI==1)
    const float* __restrict__ XrefF,  // residual x (EPI==2)
    const float* __restrict__ rowsc,  // per-row scale (EPI==2)
    __half* __restrict__ H1,          // log_alpha (EPI==1)
    __half* __restrict__ H2,          // beta_x (EPI==1)
    float*  __restrict__ O)           // final out (EPI==2)
{
    extern __shared__ char dynsm[];
    __half* smh = (__half*)dynsm;
    const uint32_t smem_u = (uint32_t)__cvta_generic_to_shared(dynsm);

    const int tid  = threadIdx.x;
    const int m0   = blockIdx.y * 128;
    const int n0   = blockIdx.x * 128;
    const int lane = tid & 31;
    const int warp = tid >> 5;
    const int wm   = (warp & 1) * 64;
    const int wn   = (warp >> 1) * 32;
    const int grp  = lane >> 2;
    const int thr  = lane & 3;

    float acc[4][4][4];
    #pragma unroll
    for (int i = 0; i < 4; i++)
        #pragma unroll
        for (int j = 0; j < 4; j++)
            #pragma unroll
            for (int r = 0; r < 4; r++) acc[i][j][r] = 0.f;

    const int KT = DN / 64;             // 16 stages of BK=64
    const int lr = tid >> 1;            // row 0..127
    const int lc = (tid & 1) * 32;      // half offset within 64-half row

    // Per-lane ldmatrix base addresses (stage 0, ks=0)
    const int arow  = lane & 15;
    const int koff8 = (lane >> 4) * 8;
    uint32_t aB[4], bB[2];
    #pragma unroll
    for (int i = 0; i < 4; i++)
        aB[i] = smem_u + (uint32_t)(((wm + i*16 + arow)*RSH + koff8) * 2);
    #pragma unroll
    for (int jj = 0; jj < 2; jj++)
        bB[jj] = smem_u + (uint32_t)(STAGE_H*2 + ((wn + jj*16 + arow)*RSH + koff8) * 2);

    auto issue = [&](int kt) {
        const int buf = kt % NST;
        const __half* Ag = A + (size_t)(m0 + lr) * DN + kt*64 + lc;
        const __half* Wg = W + (size_t)(n0 + lr) * DN + kt*64 + lc;
        __half* Asb = smh + buf * (2*STAGE_H);
        __half* Bsb = Asb + STAGE_H;
        #pragma unroll
        for (int i = 0; i < 4; i++) {
            cp16(Asb + lr*RSH + lc + i*8, Ag + i*8);
            cp16(Bsb + lr*RSH + lc + i*8, Wg + i*8);
        }
        cp_commit();
    };

    issue(0);
    issue(1);

    uint32_t af[2][4][4];    // double-buffered A fragments
    uint32_t bfr[2][4][2];   // double-buffered B fragments

    auto load_frags = [&](int ks, uint32_t stg, int pb) {
        const uint32_t ko = stg + (uint32_t)ks * 32;   // ks*16 halves
        #pragma unroll
        for (int i = 0; i < 4; i++)
            ldsm4(af[pb][i][0], af[pb][i][1], af[pb][i][2], af[pb][i][3],
                  aB[i] + ko);
        #pragma unroll
        for (int jj = 0; jj < 2; jj++) {
            uint32_t r0, r1, r2, r3;
            ldsm4(r0, r1, r2, r3, bB[jj] + ko);
            bfr[pb][2*jj][0]   = r0;
            bfr[pb][2*jj+1][0] = r1;
            bfr[pb][2*jj][1]   = r2;
            bfr[pb][2*jj+1][1] = r3;
        }
    };

    for (int kt = 0; kt < KT; ++kt) {
        if (kt + 1 < KT) asm volatile("cp.async.wait_group 1;\n");
        else             asm volatile("cp.async.wait_group 0;\n");
        __syncthreads();
        if (kt + 2 < KT) issue(kt + 2);

        const uint32_t stg = (uint32_t)((kt % NST) * STG_BYTES);

        load_frags(0, stg, 0);
        #pragma unroll
        for (int ks = 0; ks < 4; ks++) {
            if (ks < 3) load_frags(ks + 1, stg, (ks + 1) & 1);
            const int pb = ks & 1;
            #pragma unroll
            for (int i = 0; i < 4; i++)
                #pragma unroll
                for (int j = 0; j < 4; j++)
                    mma_f16(&acc[i][j][0], &af[pb][i][0], &bfr[pb][j][0]);
        }
    }

    if (EPI == 1) {
        // Epilogue: sigmoid / log / beta_x (precise exp/log, fp16 outputs)
        const float ab = sc1[0];
        const float bscale = sc2[0];
        #pragma unroll
        for (int i = 0; i < 4; i++) {
            #pragma unroll
            for (int j = 0; j < 4; j++) {
                const int col = n0 + wn + j*8 + thr*2;
                const float b0 = __ldg(bias + col);
                const float b1 = __ldg(bias + col + 1);
                #pragma unroll
                for (int h = 0; h < 2; h++) {
                    const int row = m0 + wm + i*16 + grp + h*8;
                    const float z0 = acc[i][j][2*h+0] + b0 + ab;
                    const float z1 = acc[i][j][2*h+1] + b1 + ab;
                    const float a0 = 1.0f / (1.0f + expf(-z0));
                    const float a1 = 1.0f / (1.0f + expf(-z1));
                    const float2 xn = __half22float2(*(const __half2*)(XrefH + (size_t)row*DN + col));
                    const float la0 = logf(a0 + 1e-8f);
                    const float la1 = logf(a1 + 1e-8f);
                    const float bx0 = bscale * (1.0f - a0) * xn.x;
                    const float bx1 = bscale * (1.0f - a1) * xn.y;
                    *(__half2*)(H1 + (size_t)row*DN + col) = __floats2half2_rn(la0, la1);
                    *(__half2*)(H2 + (size_t)row*DN + col) = __floats2half2_rn(bx0, bx1);
                }
            }
        }
    } else {
        // Epilogue: z = acc * r[row] + bias; tanh*0.05 + residual
        #pragma unroll
        for (int i = 0; i < 4; i++) {
            #pragma unroll
            for (int j = 0; j < 4; j++) {
                const int col = n0 + wn + j*8 + thr*2;
                const float b0 = __ldg(bias + col);
                const float b1 = __ldg(bias + col + 1);
                #pragma unroll
                for (int h = 0; h < 2; h++) {
                    const int row = m0 + wm + i*16 + grp + h*8;
                    const float r = __ldg(rowsc + row);
                    const float g0 = tanhf(acc[i][j][2*h+0] * r + b0);
                    const float g1 = tanhf(acc[i][j][2*h+1] * r + b1);
                    const float2 res = *(const float2*)(XrefF + (size_t)row*DN + col);
                    float2 o;
                    o.x = g0 * 0.05f + res.x;
                    o.y = g1 * 0.05f + res.y;
                    *(float2*)(O + (size_t)row*DN + col) = o;
                }
            }
        }
    }
}

// ---------------------------------------------------------------------------
// Scan phase 1: per (b, seg, channel-pair): segment sums (fp16 in, f32 accum)
// ---------------------------------------------------------------------------
__global__ __launch_bounds__(256) void scan_seg1(
    const __half* __restrict__ la, const __half* __restrict__ bx,
    float* __restrict__ segL, float* __restrict__ segP)
{
    const int d2 = blockIdx.x * 256 + threadIdx.x;
    const int s  = blockIdx.y;
    const int b  = blockIdx.z;
    size_t idx = (size_t)(b*TN + s*SEG) * DN + d2*2;
    float L0 = 0.f, L1 = 0.f, P0 = 0.f, P1 = 0.f;
    #pragma unroll 8
    for (int t = 0; t < SEG; t++) {
        const float2 l = __half22float2(*(const __half2*)(la + idx));
        const float2 x = __half22float2(*(const __half2*)(bx + idx));
        L0 += l.x;  L1 += l.y;
        P0 += x.x * __expf(L0);
        P1 += x.y * __expf(L1);
        idx += DN;
    }
    const size_t o = (size_t)(b*NSEG + s) * DN + d2*2;
    *(float2*)(segL + o) = make_float2(L0, L1);
    *(float2*)(segP + o) = make_float2(P0, P1);
}

// ---------------------------------------------------------------------------
// Scan phase 2: per (b, d): exclusive combine across NSEG segments.
// m = log_alpha[b, t=0, d] (cumsum non-increasing -> max at first element).
// ---------------------------------------------------------------------------
__global__ __launch_bounds__(256) void scan_seg2(
    const __half* __restrict__ la,
    const float* __restrict__ segL, const float* __restrict__ segP,
    float* __restrict__ Lb, float* __restrict__ sb)
{
    const int idx = blockIdx.x * 256 + threadIdx.x;   // 0..4095
    const int b = idx >> 10;
    const int d = idx & (DN - 1);
    const float m = __half2float(la[(size_t)b * TN * DN + d]);
    float Lex = 0.f, ss = 0.f;
    #pragma unroll
    for (int s = 0; s < NSEG; s++) {
        const size_t o = (size_t)(b*NSEG + s) * DN + d;
        Lb[o] = Lex - m;
        sb[o] = ss;
        ss  += segP[o] * __expf(Lex - m);
        Lex += segL[o];
    }
}

// ---------------------------------------------------------------------------
// Scan phase 3: final streaming pass; raw f32 output.
// ---------------------------------------------------------------------------
__global__ __launch_bounds__(256) void scan_seg3(
    const __half* __restrict__ la, const __half* __restrict__ bx,
    const float* __restrict__ Lb, const float* __restrict__ sb,
    float* __restrict__ out)
{
    const int d2 = blockIdx.x * 256 + threadIdx.x;
    const int s  = blockIdx.y;
    const int b  = blockIdx.z;
    const size_t o = (size_t)(b*NSEG + s) * DN + d2*2;
    const float2 Lb2 = *(const float2*)(Lb + o);
    const float2 sb2 = *(const float2*)(sb + o);
    float L0 = Lb2.x, L1 = Lb2.y;
    float s0 = sb2.x, s1 = sb2.y;
    size_t idx = (size_t)(b*TN + s*SEG) * DN + d2*2;
    #pragma unroll 8
    for (int t = 0; t < SEG; t++) {
        const float2 l = __half22float2(*(const __half2*)(la + idx));
        const float2 x = __half22float2(*(const __half2*)(bx + idx));
        L0 += l.x;  L1 += l.y;
        const float c0 = __expf(L0);
        const float c1 = __expf(L1);
        s0 += x.x * c0;
        s1 += x.y * c1;
        *(float2*)(out + idx) = make_float2(s0 / (c0 + 1e-8f), s1 / (c1 + 1e-8f));
        idx += DN;
    }
}

// ---------------------------------------------------------------------------
// Rowscale: per row compute r = max|out|, write r and fp16 out/r.
// One warp per row; 8 rows per block.
// ---------------------------------------------------------------------------
__global__ __launch_bounds__(256) void rowscale_kernel(
    const float* __restrict__ in, float* __restrict__ rmax,
    __half* __restrict__ outh)
{
    const int warp = threadIdx.x >> 5;
    const int lane = threadIdx.x & 31;
    const int row  = blockIdx.x * 8 + warp;

    const float4* rp = (const float4*)(in + (size_t)row * DN);
    float mx = 0.f;
    #pragma unroll
    for (int i = 0; i < 8; i++) {
        const float4 v = rp[lane + 32*i];
        mx = fmaxf(mx, fmaxf(fmaxf(fabsf(v.x), fabsf(v.y)),
                             fmaxf(fabsf(v.z), fabsf(v.w))));
    }
    #pragma unroll
    for (int o = 16; o > 0; o >>= 1)
        mx = fmaxf(mx, __shfl_xor_sync(0xffffffffu, mx, o));
    mx = fmaxf(mx, 1e-30f);
    if (lane == 0) rmax[row] = mx;
    const float inv = 1.0f / mx;

    #pragma unroll
    for (int i = 0; i < 8; i++) {
        const int c = lane + 32*i;
        const float4 v = rp[c];
        __half2 h01 = __floats2half2_rn(v.x * inv, v.y * inv);
        __half2 h23 = __floats2half2_rn(v.z * inv, v.w * inv);
        uint2 pk;
        pk.x = *(uint32_t*)&h01;
        pk.y = *(uint32_t*)&h23;
        *(uint2*)(outh + (size_t)row * DN + c*4) = pk;
    }
}

// ---------------------------------------------------------------------------
// Launch
// ---------------------------------------------------------------------------
extern "C" void kernel_launch(void* const* d_in, const int* in_sizes, int n_in,
                              void* d_out, int out_size)
{
    const float* x    = (const float*)d_in[0];
    const float* ln_w = (const float*)d_in[1];
    const float* ln_b = (const float*)d_in[2];
    const float* Wf   = (const float*)d_in[3];
    const float* bf   = (const float*)d_in[4];
    const float* Wr   = (const float*)d_in[5];
    const float* br   = (const float*)d_in[6];
    const float* ab   = (const float*)d_in[7];
    const float* bs   = (const float*)d_in[8];
    float* out = (float*)d_out;

    float *p_scan, *p_rmax, *p_segL, *p_segP, *p_Lb, *p_sb;
    __half *p_xnorm, *p_la, *p_bx, *p_wf, *p_wrh, *p_scanh;
    cudaGetSymbolAddress((void**)&p_xnorm, g_xnorm);
    cudaGetSymbolAddress((void**)&p_la,    g_la);
    cudaGetSymbolAddress((void**)&p_bx,    g_bx);
    cudaGetSymbolAddress((void**)&p_scan,  g_scan);
    cudaGetSymbolAddress((void**)&p_scanh, g_scanh);
    cudaGetSymbolAddress((void**)&p_rmax,  g_rmax);
    cudaGetSymbolAddress((void**)&p_wf,    g_wf);
    cudaGetSymbolAddress((void**)&p_wrh,   g_wrh);
    cudaGetSymbolAddress((void**)&p_segL,  g_segL);
    cudaGetSymbolAddress((void**)&p_segP,  g_segP);
    cudaGetSymbolAddress((void**)&p_Lb,    g_Lb);
    cudaGetSymbolAddress((void**)&p_sb,    g_sb);

    cudaFuncSetAttribute(gemm_h<1>, cudaFuncAttributeMaxDynamicSharedMemorySize, GEMMH_SMEM);
    cudaFuncSetAttribute(gemm_h<2>, cudaFuncAttributeMaxDynamicSharedMemorySize, GEMMH_SMEM);

    // 0) Weight conversions (~6us total)
    cvt_h_kernel<<<(DN*DN/4)/256, 256>>>(Wf, p_wf);
    cvt_h_kernel<<<(DN*DN/4)/256, 256>>>(Wr, p_wrh);

    // 1) LayerNorm (warp-per-row, fp16 output)
    ln_kernel<<<MN/8, 256>>>(x, ln_w, ln_b, p_xnorm);

    // 2) GEMM1 (fp16, BK=64 stages, pipelined fragments): fused epilogue
    dim3 ggrid(DN/128, MN/128);
    gemm_h<1><<<ggrid, 256, GEMMH_SMEM>>>(
        p_xnorm, p_wf, bf, ab, bs, p_xnorm, nullptr, nullptr,
        p_la, p_bx, nullptr);

    // 3) Segmented scan over T (SEG=64, fp16 streams, f32 accumulation)
    dim3 sgrid(DN/512, NSEG, BZ);
    scan_seg1<<<sgrid, 256>>>(p_la, p_bx, p_segL, p_segP);
    scan_seg2<<<(BZ*DN)/256, 256>>>(p_la, p_segL, p_segP, p_Lb, p_sb);
    scan_seg3<<<sgrid, 256>>>(p_la, p_bx, p_Lb, p_sb, p_scan);

    // 3b) Per-row scale + fp16 conversion of scan output
    rowscale_kernel<<<MN/8, 256>>>(p_scan, p_rmax, p_scanh);

    // 4) GEMM2 (fp16, row-rescaled): tanh(scan @ Wr^T + br)*0.05 + x
    gemm_h<2><<<ggrid, 256, GEMMH_SMEM>>>(
        p_scanh, p_wrh, br, nullptr, nullptr, nullptr, x, p_rmax,
        nullptr, nullptr, out);
}

// round 10
// speedup vs baseline: 1.0422x; 1.0422x over previous
#include <cuda_runtime.h>
#include <cuda_fp16.h>
#include <cstdint>

// Problem constants (fixed shapes)
#define BZ 4
#define TN 4096
#define DN 1024
#define MN (BZ*TN)        // 16384 rows
#define SEG 64
#define NSEG (TN/SEG)     // 64

// ---------------------------------------------------------------------------
// Scratch (static __device__ arrays; no allocation allowed)
// ---------------------------------------------------------------------------
__device__ __half g_xnorm[(size_t)MN*DN];   // fp16 LN output
__device__ __half g_la   [(size_t)MN*DN];   // fp16 log_alpha
__device__ __half g_bx   [(size_t)MN*DN];   // fp16 beta_x
__device__ float  g_scan [(size_t)MN*DN];   // f32 scan output
__device__ __half g_scanh[(size_t)MN*DN];   // fp16 row-scaled scan output
__device__ float  g_rmax [MN];              // per-row scale
__device__ __half g_wf   [(size_t)DN*DN];   // fp16 Wf
__device__ __half g_wrh  [(size_t)DN*DN];   // fp16 Wr
__device__ float  g_segL[BZ*NSEG*DN];
__device__ float  g_segP[BZ*NSEG*DN];
__device__ float  g_Lb  [BZ*NSEG*DN];
__device__ float  g_sb  [BZ*NSEG*DN];

// ---------------------------------------------------------------------------
// Helpers
// ---------------------------------------------------------------------------
__device__ __forceinline__ void cp16(void* smem, const void* g) {
    uint32_t s = (uint32_t)__cvta_generic_to_shared(smem);
    asm volatile("cp.async.cg.shared.global [%0], [%1], 16;\n" :: "r"(s), "l"(g));
}
__device__ __forceinline__ void cp_commit() {
    asm volatile("cp.async.commit_group;\n");
}
__device__ __forceinline__ void ldsm4(uint32_t& r0, uint32_t& r1, uint32_t& r2,
                                      uint32_t& r3, uint32_t addr) {
    asm volatile("ldmatrix.sync.aligned.m8n8.x4.shared.b16 {%0,%1,%2,%3}, [%4];\n"
                 : "=r"(r0), "=r"(r1), "=r"(r2), "=r"(r3) : "r"(addr));
}
__device__ __forceinline__ void mma_f16(float* c, const uint32_t* a, const uint32_t* b) {
    asm volatile(
        "mma.sync.aligned.m16n8k16.row.col.f32.f16.f16.f32 "
        "{%0,%1,%2,%3}, {%4,%5,%6,%7}, {%8,%9}, {%0,%1,%2,%3};\n"
        : "+f"(c[0]), "+f"(c[1]), "+f"(c[2]), "+f"(c[3])
        : "r"(a[0]), "r"(a[1]), "r"(a[2]), "r"(a[3]),
          "r"(b[0]), "r"(b[1]));
}

// ---------------------------------------------------------------------------
// Kernel 0: convert f32 weight matrix to fp16
// ---------------------------------------------------------------------------
__global__ __launch_bounds__(256) void cvt_h_kernel(
    const float* __restrict__ in, __half* __restrict__ out)
{
    const int i = blockIdx.x * 256 + threadIdx.x;
    const float4 v = ((const float4*)in)[i];
    __half2 h01 = __floats2half2_rn(v.x, v.y);
    __half2 h23 = __floats2half2_rn(v.z, v.w);
    uint2 pk;
    pk.x = *(uint32_t*)&h01;
    pk.y = *(uint32_t*)&h23;
    *(uint2*)(out + (size_t)i * 4) = pk;
}

// ---------------------------------------------------------------------------
// Kernel 1: LayerNorm, one WARP per row, fp16 output.
// ---------------------------------------------------------------------------
__global__ __launch_bounds__(256) void ln_kernel(
    const float* __restrict__ x, const float* __restrict__ w,
    const float* __restrict__ b, __half* __restrict__ y)
{
    const int warp = threadIdx.x >> 5;
    const int lane = threadIdx.x & 31;
    const int row  = blockIdx.x * 8 + warp;

    const float4* xr = (const float4*)(x + (size_t)row * DN);

    float s = 0.f;
    #pragma unroll
    for (int i = 0; i < 8; i++) {
        const float4 v = xr[lane + 32*i];
        s += (v.x + v.y) + (v.z + v.w);
    }
    #pragma unroll
    for (int o = 16; o > 0; o >>= 1) s += __shfl_xor_sync(0xffffffffu, s, o);
    const float mu = s * (1.0f / DN);

    float s2 = 0.f;
    #pragma unroll
    for (int i = 0; i < 8; i++) {
        const float4 v = xr[lane + 32*i];
        const float d0 = v.x - mu, d1 = v.y - mu, d2 = v.z - mu, d3 = v.w - mu;
        s2 += (d0*d0 + d1*d1) + (d2*d2 + d3*d3);
    }
    #pragma unroll
    for (int o = 16; o > 0; o >>= 1) s2 += __shfl_xor_sync(0xffffffffu, s2, o);
    const float rs = rsqrtf(s2 * (1.0f / DN) + 1e-5f);

    const float4* wv = (const float4*)w;
    const float4* bv = (const float4*)b;
    #pragma unroll
    for (int i = 0; i < 8; i++) {
        const int c = lane + 32*i;
        const float4 v  = xr[c];
        const float4 w4 = wv[c];
        const float4 b4 = bv[c];
        __half2 h01 = __floats2half2_rn((v.x - mu) * rs * w4.x + b4.x,
                                        (v.y - mu) * rs * w4.y + b4.y);
        __half2 h23 = __floats2half2_rn((v.z - mu) * rs * w4.z + b4.z,
                                        (v.w - mu) * rs * w4.w + b4.w);
        uint2 pk;
        pk.x = *(uint32_t*)&h01;
        pk.y = *(uint32_t*)&h23;
        *(uint2*)(y + (size_t)row * DN + c*4) = pk;
    }
}

// ---------------------------------------------------------------------------
// fp16 GEMM (shared body): C[m,n] = sum_k A[m,k]*W[n,k], fp16 in, f32 accum.
// 128x128 tile, BK=32, 5-stage cp.async ring (prefetch depth 3),
// ldmatrix fragments, 2 CTAs/SM.
// EPI==1: sigmoid/log_alpha/beta_x epilogue (fp16 out).
// EPI==2: per-row-rescale + tanh*0.05 + residual (f32 out).
// ---------------------------------------------------------------------------
#define RS1 40                       // smem row stride in halves (80B)
#define STAGE1_H (128*RS1)           // halves per operand per stage
#define STG_BYTES (2*STAGE1_H*2)     // A+B bytes per stage = 20480
#define NST 5
#define GEMMH_SMEM (NST*STG_BYTES)   // 102400 (2 CTAs/SM)

template<int EPI>
__global__ __launch_bounds__(256, 2) void gemm_h(
    const __half* __restrict__ A, const __half* __restrict__ W,
    const float* __restrict__ bias,
    const float* __restrict__ sc1,    // alpha_bias (EPI==1)
    const float* __restrict__ sc2,    // beta_scale (EPI==1)
    const __half* __restrict__ XrefH, // x_norm fp16 (EPI==1)
    const float* __restrict__ XrefF,  // residual x (EPI==2)
    const float* __restrict__ rowsc,  // per-row scale (EPI==2)
    __half* __restrict__ H1,          // log_alpha (EPI==1)
    __half* __restrict__ H2,          // beta_x (EPI==1)
    float*  __restrict__ O)           // final out (EPI==2)
{
    extern __shared__ char dynsm[];
    __half* smh = (__half*)dynsm;
    const uint32_t smem_u = (uint32_t)__cvta_generic_to_shared(dynsm);

    const int tid  = threadIdx.x;
    const int m0   = blockIdx.y * 128;
    const int n0   = blockIdx.x * 128;
    const int lane = tid & 31;
    const int warp = tid >> 5;
    const int wm   = (warp & 1) * 64;
    const int wn   = (warp >> 1) * 32;
    const int grp  = lane >> 2;
    const int thr  = lane & 3;

    float acc[4][4][4];
    #pragma unroll
    for (int i = 0; i < 4; i++)
        #pragma unroll
        for (int j = 0; j < 4; j++)
            #pragma unroll
            for (int r = 0; r < 4; r++) acc[i][j][r] = 0.f;

    const int KT = DN / 32;
    const int lr = tid >> 1;            // row 0..127
    const int lc = (tid & 1) * 16;      // half offset within 32-half chunk

    // Per-lane ldmatrix base addresses (stage 0)
    const int arow  = lane & 15;
    const int koff8 = (lane >> 4) * 8;
    uint32_t aB[4], bB[2];
    #pragma unroll
    for (int i = 0; i < 4; i++)
        aB[i] = smem_u + (uint32_t)(((wm + i*16 + arow)*RS1 + koff8) * 2);
    #pragma unroll
    for (int jj = 0; jj < 2; jj++)
        bB[jj] = smem_u + (uint32_t)(STAGE1_H*2 + ((wn + jj*16 + arow)*RS1 + koff8) * 2);

    auto issue = [&](int kt) {
        const int buf = kt % NST;
        const __half* Ag = A + (size_t)(m0 + lr) * DN + kt*32 + lc;
        const __half* Wg = W + (size_t)(n0 + lr) * DN + kt*32 + lc;
        __half* Asb = smh + buf * (2*STAGE1_H);
        __half* Bsb = Asb + STAGE1_H;
        #pragma unroll
        for (int i = 0; i < 2; i++) {
            cp16(Asb + lr*RS1 + lc + i*8, Ag + i*8);
            cp16(Bsb + lr*RS1 + lc + i*8, Wg + i*8);
        }
        cp_commit();
    };

    issue(0);
    issue(1);
    issue(2);
    issue(3);

    for (int kt = 0; kt < KT; ++kt) {
        if      (kt + 4 <= KT - 1) asm volatile("cp.async.wait_group 3;\n");
        else if (kt + 3 <= KT - 1) asm volatile("cp.async.wait_group 2;\n");
        else if (kt + 2 <= KT - 1) asm volatile("cp.async.wait_group 1;\n");
        else                       asm volatile("cp.async.wait_group 0;\n");
        __syncthreads();
        if (kt + 4 < KT) issue(kt + 4);

        const uint32_t stg = (uint32_t)((kt % NST) * STG_BYTES);

        #pragma unroll
        for (int ks = 0; ks < 2; ks++) {
            uint32_t af[4][4];
            uint32_t bfr[4][2];
            #pragma unroll
            for (int i = 0; i < 4; i++)
                ldsm4(af[i][0], af[i][1], af[i][2], af[i][3],
                      aB[i] + stg + ks*32);
            #pragma unroll
            for (int jj = 0; jj < 2; jj++) {
                uint32_t r0, r1, r2, r3;
                ldsm4(r0, r1, r2, r3, bB[jj] + stg + ks*32);
                bfr[2*jj][0]   = r0;
                bfr[2*jj+1][0] = r1;
                bfr[2*jj][1]   = r2;
                bfr[2*jj+1][1] = r3;
            }
            #pragma unroll
            for (int i = 0; i < 4; i++)
                #pragma unroll
                for (int j = 0; j < 4; j++)
                    mma_f16(&acc[i][j][0], &af[i][0], &bfr[j][0]);
        }
    }

    if (EPI == 1) {
        // Epilogue: sigmoid / log / beta_x (precise exp/log, fp16 outputs)
        const float ab = sc1[0];
        const float bscale = sc2[0];
        #pragma unroll
        for (int i = 0; i < 4; i++) {
            #pragma unroll
            for (int j = 0; j < 4; j++) {
                const int col = n0 + wn + j*8 + thr*2;
                const float b0 = __ldg(bias + col);
                const float b1 = __ldg(bias + col + 1);
                #pragma unroll
                for (int h = 0; h < 2; h++) {
                    const int row = m0 + wm + i*16 + grp + h*8;
                    const float z0 = acc[i][j][2*h+0] + b0 + ab;
                    const float z1 = acc[i][j][2*h+1] + b1 + ab;
                    const float a0 = 1.0f / (1.0f + expf(-z0));
                    const float a1 = 1.0f / (1.0f + expf(-z1));
                    const float2 xn = __half22float2(*(const __half2*)(XrefH + (size_t)row*DN + col));
                    const float la0 = logf(a0 + 1e-8f);
                    const float la1 = logf(a1 + 1e-8f);
                    const float bx0 = bscale * (1.0f - a0) * xn.x;
                    const float bx1 = bscale * (1.0f - a1) * xn.y;
                    *(__half2*)(H1 + (size_t)row*DN + col) = __floats2half2_rn(la0, la1);
                    *(__half2*)(H2 + (size_t)row*DN + col) = __floats2half2_rn(bx0, bx1);
                }
            }
        }
    } else {
        // Epilogue: z = acc * r[row] + bias; tanh*0.05 + residual
        #pragma unroll
        for (int i = 0; i < 4; i++) {
            #pragma unroll
            for (int j = 0; j < 4; j++) {
                const int col = n0 + wn + j*8 + thr*2;
                const float b0 = __ldg(bias + col);
                const float b1 = __ldg(bias + col + 1);
                #pragma unroll
                for (int h = 0; h < 2; h++) {
                    const int row = m0 + wm + i*16 + grp + h*8;
                    const float r = __ldg(rowsc + row);
                    const float g0 = tanhf(acc[i][j][2*h+0] * r + b0);
                    const float g1 = tanhf(acc[i][j][2*h+1] * r + b1);
                    const float2 res = *(const float2*)(XrefF + (size_t)row*DN + col);
                    float2 o;
                    o.x = g0 * 0.05f + res.x;
                    o.y = g1 * 0.05f + res.y;
                    *(float2*)(O + (size_t)row*DN + col) = o;
                }
            }
        }
    }
}

// ---------------------------------------------------------------------------
// Scan phase 1: per (b, seg, channel-pair): segment sums (fp16 in, f32 accum)
// ---------------------------------------------------------------------------
__global__ __launch_bounds__(256) void scan_seg1(
    const __half* __restrict__ la, const __half* __restrict__ bx,
    float* __restrict__ segL, float* __restrict__ segP)
{
    const int d2 = blockIdx.x * 256 + threadIdx.x;
    const int s  = blockIdx.y;
    const int b  = blockIdx.z;
    size_t idx = (size_t)(b*TN + s*SEG) * DN + d2*2;
    float L0 = 0.f, L1 = 0.f, P0 = 0.f, P1 = 0.f;
    #pragma unroll 8
    for (int t = 0; t < SEG; t++) {
        const float2 l = __half22float2(*(const __half2*)(la + idx));
        const float2 x = __half22float2(*(const __half2*)(bx + idx));
        L0 += l.x;  L1 += l.y;
        P0 += x.x * __expf(L0);
        P1 += x.y * __expf(L1);
        idx += DN;
    }
    const size_t o = (size_t)(b*NSEG + s) * DN + d2*2;
    *(float2*)(segL + o) = make_float2(L0, L1);
    *(float2*)(segP + o) = make_float2(P0, P1);
}

// ---------------------------------------------------------------------------
// Scan phase 2: per (b, d): exclusive combine across NSEG segments.
// m = log_alpha[b, t=0, d] (cumsum non-increasing -> max at first element).
// ---------------------------------------------------------------------------
__global__ __launch_bounds__(256) void scan_seg2(
    const __half* __restrict__ la,
    const float* __restrict__ segL, const float* __restrict__ segP,
    float* __restrict__ Lb, float* __restrict__ sb)
{
    const int idx = blockIdx.x * 256 + threadIdx.x;   // 0..4095
    const int b = idx >> 10;
    const int d = idx & (DN - 1);
    const float m = __half2float(la[(size_t)b * TN * DN + d]);
    float Lex = 0.f, ss = 0.f;
    #pragma unroll
    for (int s = 0; s < NSEG; s++) {
        const size_t o = (size_t)(b*NSEG + s) * DN + d;
        Lb[o] = Lex - m;
        sb[o] = ss;
        ss  += segP[o] * __expf(Lex - m);
        Lex += segL[o];
    }
}

// ---------------------------------------------------------------------------
// Scan phase 3: final streaming pass; raw f32 output.
// ---------------------------------------------------------------------------
__global__ __launch_bounds__(256) void scan_seg3(
    const __half* __restrict__ la, const __half* __restrict__ bx,
    const float* __restrict__ Lb, const float* __restrict__ sb,
    float* __restrict__ out)
{
    const int d2 = blockIdx.x * 256 + threadIdx.x;
    const int s  = blockIdx.y;
    const int b  = blockIdx.z;
    const size_t o = (size_t)(b*NSEG + s) * DN + d2*2;
    const float2 Lb2 = *(const float2*)(Lb + o);
    const float2 sb2 = *(const float2*)(sb + o);
    float L0 = Lb2.x, L1 = Lb2.y;
    float s0 = sb2.x, s1 = sb2.y;
    size_t idx = (size_t)(b*TN + s*SEG) * DN + d2*2;
    #pragma unroll 8
    for (int t = 0; t < SEG; t++) {
        const float2 l = __half22float2(*(const __half2*)(la + idx));
        const float2 x = __half22float2(*(const __half2*)(bx + idx));
        L0 += l.x;  L1 += l.y;
        const float c0 = __expf(L0);
        const float c1 = __expf(L1);
        s0 += x.x * c0;
        s1 += x.y * c1;
        *(float2*)(out + idx) = make_float2(s0 / (c0 + 1e-8f), s1 / (c1 + 1e-8f));
        idx += DN;
    }
}

// ---------------------------------------------------------------------------
// Rowscale: per row compute r = max|out|, write r and fp16 out/r.
// One warp per row; 8 rows per block.
// ---------------------------------------------------------------------------
__global__ __launch_bounds__(256) void rowscale_kernel(
    const float* __restrict__ in, float* __restrict__ rmax,
    __half* __restrict__ outh)
{
    const int warp = threadIdx.x >> 5;
    const int lane = threadIdx.x & 31;
    const int row  = blockIdx.x * 8 + warp;

    const float4* rp = (const float4*)(in + (size_t)row * DN);
    float mx = 0.f;
    #pragma unroll
    for (int i = 0; i < 8; i++) {
        const float4 v = rp[lane + 32*i];
        mx = fmaxf(mx, fmaxf(fmaxf(fabsf(v.x), fabsf(v.y)),
                             fmaxf(fabsf(v.z), fabsf(v.w))));
    }
    #pragma unroll
    for (int o = 16; o > 0; o >>= 1)
        mx = fmaxf(mx, __shfl_xor_sync(0xffffffffu, mx, o));
    mx = fmaxf(mx, 1e-30f);
    if (lane == 0) rmax[row] = mx;
    const float inv = 1.0f / mx;

    #pragma unroll
    for (int i = 0; i < 8; i++) {
        const int c = lane + 32*i;
        const float4 v = rp[c];
        __half2 h01 = __floats2half2_rn(v.x * inv, v.y * inv);
        __half2 h23 = __floats2half2_rn(v.z * inv, v.w * inv);
        uint2 pk;
        pk.x = *(uint32_t*)&h01;
        pk.y = *(uint32_t*)&h23;
        *(uint2*)(outh + (size_t)row * DN + c*4) = pk;
    }
}

// ---------------------------------------------------------------------------
// Launch
// ---------------------------------------------------------------------------
extern "C" void kernel_launch(void* const* d_in, const int* in_sizes, int n_in,
                              void* d_out, int out_size)
{
    const float* x    = (const float*)d_in[0];
    const float* ln_w = (const float*)d_in[1];
    const float* ln_b = (const float*)d_in[2];
    const float* Wf   = (const float*)d_in[3];
    const float* bf   = (const float*)d_in[4];
    const float* Wr   = (const float*)d_in[5];
    const float* br   = (const float*)d_in[6];
    const float* ab   = (const float*)d_in[7];
    const float* bs   = (const float*)d_in[8];
    float* out = (float*)d_out;

    float *p_scan, *p_rmax, *p_segL, *p_segP, *p_Lb, *p_sb;
    __half *p_xnorm, *p_la, *p_bx, *p_wf, *p_wrh, *p_scanh;
    cudaGetSymbolAddress((void**)&p_xnorm, g_xnorm);
    cudaGetSymbolAddress((void**)&p_la,    g_la);
    cudaGetSymbolAddress((void**)&p_bx,    g_bx);
    cudaGetSymbolAddress((void**)&p_scan,  g_scan);
    cudaGetSymbolAddress((void**)&p_scanh, g_scanh);
    cudaGetSymbolAddress((void**)&p_rmax,  g_rmax);
    cudaGetSymbolAddress((void**)&p_wf,    g_wf);
    cudaGetSymbolAddress((void**)&p_wrh,   g_wrh);
    cudaGetSymbolAddress((void**)&p_segL,  g_segL);
    cudaGetSymbolAddress((void**)&p_segP,  g_segP);
    cudaGetSymbolAddress((void**)&p_Lb,    g_Lb);
    cudaGetSymbolAddress((void**)&p_sb,    g_sb);

    cudaFuncSetAttribute(gemm_h<1>, cudaFuncAttributeMaxDynamicSharedMemorySize, GEMMH_SMEM);
    cudaFuncSetAttribute(gemm_h<2>, cudaFuncAttributeMaxDynamicSharedMemorySize, GEMMH_SMEM);

    // 0) Weight conversions (~6us total)
    cvt_h_kernel<<<(DN*DN/4)/256, 256>>>(Wf, p_wf);
    cvt_h_kernel<<<(DN*DN/4)/256, 256>>>(Wr, p_wrh);

    // 1) LayerNorm (warp-per-row, fp16 output)
    ln_kernel<<<MN/8, 256>>>(x, ln_w, ln_b, p_xnorm);

    // 2) GEMM1 (fp16 + ldmatrix, 5-stage ring, 2 CTAs/SM): fused epilogue
    dim3 ggrid(DN/128, MN/128);
    gemm_h<1><<<ggrid, 256, GEMMH_SMEM>>>(
        p_xnorm, p_wf, bf, ab, bs, p_xnorm, nullptr, nullptr,
        p_la, p_bx, nullptr);

    // 3) Segmented scan over T (SEG=64, fp16 streams, f32 accumulation)
    dim3 sgrid(DN/512, NSEG, BZ);
    scan_seg1<<<sgrid, 256>>>(p_la, p_bx, p_segL, p_segP);
    scan_seg2<<<(BZ*DN)/256, 256>>>(p_la, p_segL, p_segP, p_Lb, p_sb);
    scan_seg3<<<sgrid, 256>>>(p_la, p_bx, p_Lb, p_sb, p_scan);

    // 3b) Per-row scale + fp16 conversion of scan output
    rowscale_kernel<<<MN/8, 256>>>(p_scan, p_rmax, p_scanh);

    // 4) GEMM2 (fp16 + ldmatrix, row-rescaled): tanh(scan @ Wr^T + br)*0.05 + x
    gemm_h<2><<<ggrid, 256, GEMMH_SMEM>>>(
        p_scanh, p_wrh, br, nullptr, nullptr, nullptr, x, p_rmax,
        nullptr, nullptr, out);
}

// round 11
// speedup vs baseline: 1.0898x; 1.0457x over previous
#include <cuda_runtime.h>
#include <cuda_fp16.h>
#include <cstdint>

// Problem constants (fixed shapes)
#define BZ 4
#define TN 4096
#define DN 1024
#define MN (BZ*TN)        // 16384 rows
#define SEG 64
#define NSEG (TN/SEG)     // 64

// ---------------------------------------------------------------------------
// Scratch (static __device__ arrays; no allocation allowed)
// ---------------------------------------------------------------------------
__device__ __half g_xnorm[(size_t)MN*DN];   // fp16 LN output
__device__ __half g_la   [(size_t)MN*DN];   // fp16 log_alpha
__device__ __half g_bx   [(size_t)MN*DN];   // fp16 beta_x
__device__ float  g_scan [(size_t)MN*DN];   // f32 scan output
__device__ __half g_scanh[(size_t)MN*DN];   // fp16 row-scaled scan output
__device__ float  g_rmax [MN];              // per-row scale
__device__ __half g_wf   [(size_t)DN*DN];   // fp16 Wf
__device__ __half g_wrh  [(size_t)DN*DN];   // fp16 Wr
__device__ float  g_segL[BZ*NSEG*DN];
__device__ float  g_segP[BZ*NSEG*DN];
__device__ float  g_Lb  [BZ*NSEG*DN];
__device__ float  g_sb  [BZ*NSEG*DN];

// ---------------------------------------------------------------------------
// Helpers
// ---------------------------------------------------------------------------
__device__ __forceinline__ void cp16s(uint32_t s, const void* g) {
    asm volatile("cp.async.cg.shared.global [%0], [%1], 16;\n" :: "r"(s), "l"(g));
}
__device__ __forceinline__ void cp_commit() {
    asm volatile("cp.async.commit_group;\n");
}
__device__ __forceinline__ void ldsm4(uint32_t& r0, uint32_t& r1, uint32_t& r2,
                                      uint32_t& r3, uint32_t addr) {
    asm volatile("ldmatrix.sync.aligned.m8n8.x4.shared.b16 {%0,%1,%2,%3}, [%4];\n"
                 : "=r"(r0), "=r"(r1), "=r"(r2), "=r"(r3) : "r"(addr));
}
__device__ __forceinline__ void mma_f16(float* c, const uint32_t* a, const uint32_t* b) {
    asm volatile(
        "mma.sync.aligned.m16n8k16.row.col.f32.f16.f16.f32 "
        "{%0,%1,%2,%3}, {%4,%5,%6,%7}, {%8,%9}, {%0,%1,%2,%3};\n"
        : "+f"(c[0]), "+f"(c[1]), "+f"(c[2]), "+f"(c[3])
        : "r"(a[0]), "r"(a[1]), "r"(a[2]), "r"(a[3]),
          "r"(b[0]), "r"(b[1]));
}

// ---------------------------------------------------------------------------
// Kernel 0: convert f32 weight matrix to fp16
// ---------------------------------------------------------------------------
__global__ __launch_bounds__(256) void cvt_h_kernel(
    const float* __restrict__ in, __half* __restrict__ out)
{
    const int i = blockIdx.x * 256 + threadIdx.x;
    const float4 v = ((const float4*)in)[i];
    __half2 h01 = __floats2half2_rn(v.x, v.y);
    __half2 h23 = __floats2half2_rn(v.z, v.w);
    uint2 pk;
    pk.x = *(uint32_t*)&h01;
    pk.y = *(uint32_t*)&h23;
    *(uint2*)(out + (size_t)i * 4) = pk;
}

// ---------------------------------------------------------------------------
// Kernel 1: LayerNorm, one WARP per row, fp16 output.
// ---------------------------------------------------------------------------
__global__ __launch_bounds__(256) void ln_kernel(
    const float* __restrict__ x, const float* __restrict__ w,
    const float* __restrict__ b, __half* __restrict__ y)
{
    const int warp = threadIdx.x >> 5;
    const int lane = threadIdx.x & 31;
    const int row  = blockIdx.x * 8 + warp;

    const float4* xr = (const float4*)(x + (size_t)row * DN);

    float s = 0.f;
    #pragma unroll
    for (int i = 0; i < 8; i++) {
        const float4 v = xr[lane + 32*i];
        s += (v.x + v.y) + (v.z + v.w);
    }
    #pragma unroll
    for (int o = 16; o > 0; o >>= 1) s += __shfl_xor_sync(0xffffffffu, s, o);
    const float mu = s * (1.0f / DN);

    float s2 = 0.f;
    #pragma unroll
    for (int i = 0; i < 8; i++) {
        const float4 v = xr[lane + 32*i];
        const float d0 = v.x - mu, d1 = v.y - mu, d2 = v.z - mu, d3 = v.w - mu;
        s2 += (d0*d0 + d1*d1) + (d2*d2 + d3*d3);
    }
    #pragma unroll
    for (int o = 16; o > 0; o >>= 1) s2 += __shfl_xor_sync(0xffffffffu, s2, o);
    const float rs = rsqrtf(s2 * (1.0f / DN) + 1e-5f);

    const float4* wv = (const float4*)w;
    const float4* bv = (const float4*)b;
    #pragma unroll
    for (int i = 0; i < 8; i++) {
        const int c = lane + 32*i;
        const float4 v  = xr[c];
        const float4 w4 = wv[c];
        const float4 b4 = bv[c];
        __half2 h01 = __floats2half2_rn((v.x - mu) * rs * w4.x + b4.x,
                                        (v.y - mu) * rs * w4.y + b4.y);
        __half2 h23 = __floats2half2_rn((v.z - mu) * rs * w4.z + b4.z,
                                        (v.w - mu) * rs * w4.w + b4.w);
        uint2 pk;
        pk.x = *(uint32_t*)&h01;
        pk.y = *(uint32_t*)&h23;
        *(uint2*)(y + (size_t)row * DN + c*4) = pk;
    }
}

// ---------------------------------------------------------------------------
// fp16 GEMM (shared body): C[m,n] = sum_k A[m,k]*W[n,k], fp16 in, f32 accum.
// 128x128 tile, BK=32, 4-stage cp.async ring, ldmatrix fragments, 2 CTAs/SM.
// kt-loop unrolled 4x so stage offsets are immediates (ALU reduction).
// EPI==1: sigmoid/log_alpha/beta_x epilogue (fp16 out).
// EPI==2: per-row-rescale + tanh*0.05 + residual (f32 out).
// ---------------------------------------------------------------------------
#define RS1 40                       // smem row stride in halves (80B)
#define STAGE1_H (128*RS1)           // halves per operand per stage
#define STG_BYTES (2*STAGE1_H*2)     // A+B bytes per stage = 20480
#define NST 4
#define GEMMH_SMEM (NST*STG_BYTES)   // 81920 (2 CTAs/SM)

template<int EPI>
__global__ __launch_bounds__(256, 2) void gemm_h(
    const __half* __restrict__ A, const __half* __restrict__ W,
    const float* __restrict__ bias,
    const float* __restrict__ sc1,    // alpha_bias (EPI==1)
    const float* __restrict__ sc2,    // beta_scale (EPI==1)
    const __half* __restrict__ XrefH, // x_norm fp16 (EPI==1)
    const float* __restrict__ XrefF,  // residual x (EPI==2)
    const float* __restrict__ rowsc,  // per-row scale (EPI==2)
    __half* __restrict__ H1,          // log_alpha (EPI==1)
    __half* __restrict__ H2,          // beta_x (EPI==1)
    float*  __restrict__ O)           // final out (EPI==2)
{
    extern __shared__ char dynsm[];
    const uint32_t smem_u = (uint32_t)__cvta_generic_to_shared(dynsm);

    const int tid  = threadIdx.x;
    const int m0   = blockIdx.y * 128;
    const int n0   = blockIdx.x * 128;
    const int lane = tid & 31;
    const int warp = tid >> 5;
    const int wm   = (warp & 1) * 64;
    const int wn   = (warp >> 1) * 32;
    const int grp  = lane >> 2;
    const int thr  = lane & 3;

    float acc[4][4][4];
    #pragma unroll
    for (int i = 0; i < 4; i++)
        #pragma unroll
        for (int j = 0; j < 4; j++)
            #pragma unroll
            for (int r = 0; r < 4; r++) acc[i][j][r] = 0.f;

    const int KT = DN / 32;
    const int lr = tid >> 1;            // row 0..127
    const int lc = (tid & 1) * 16;      // half offset within 32-half chunk

    // Precomputed cp.async destination addresses (uint32 shared space)
    const uint32_t awr = smem_u + (uint32_t)((lr*RS1 + lc) * 2);
    const uint32_t bwr = awr + (uint32_t)(STAGE1_H * 2);
    // Fixed global row pointers (immediate offsets after unroll)
    const __half* Arow = A + (size_t)(m0 + lr) * DN + lc;
    const __half* Wrow = W + (size_t)(n0 + lr) * DN + lc;

    // Per-lane ldmatrix base addresses (stage 0)
    const int arow  = lane & 15;
    const int koff8 = (lane >> 4) * 8;
    uint32_t aB[4], bB[2];
    #pragma unroll
    for (int i = 0; i < 4; i++)
        aB[i] = smem_u + (uint32_t)(((wm + i*16 + arow)*RS1 + koff8) * 2);
    #pragma unroll
    for (int jj = 0; jj < 2; jj++)
        bB[jj] = smem_u + (uint32_t)(STAGE1_H*2 + ((wn + jj*16 + arow)*RS1 + koff8) * 2);

    auto issue = [&](int kt) {
        const uint32_t buf = (uint32_t)(kt & 3) * STG_BYTES;
        const __half* Ag = Arow + kt * 32;
        const __half* Wg = Wrow + kt * 32;
        cp16s(awr + buf,      Ag);
        cp16s(awr + buf + 16, Ag + 8);
        cp16s(bwr + buf,      Wg);
        cp16s(bwr + buf + 16, Wg + 8);
        cp_commit();
    };

    issue(0);
    issue(1);
    issue(2);

    #pragma unroll 4
    for (int kt = 0; kt < KT; ++kt) {
        if (kt + 3 < KT) asm volatile("cp.async.wait_group 2;\n");
        else             asm volatile("cp.async.wait_group 0;\n");
        __syncthreads();
        if (kt + 3 < KT) issue(kt + 3);

        const uint32_t stg = (uint32_t)((kt & 3) * STG_BYTES);

        #pragma unroll
        for (int ks = 0; ks < 2; ks++) {
            uint32_t af[4][4];
            uint32_t bfr[4][2];
            #pragma unroll
            for (int i = 0; i < 4; i++)
                ldsm4(af[i][0], af[i][1], af[i][2], af[i][3],
                      aB[i] + stg + ks*32);
            #pragma unroll
            for (int jj = 0; jj < 2; jj++) {
                uint32_t r0, r1, r2, r3;
                ldsm4(r0, r1, r2, r3, bB[jj] + stg + ks*32);
                bfr[2*jj][0]   = r0;
                bfr[2*jj+1][0] = r1;
                bfr[2*jj][1]   = r2;
                bfr[2*jj+1][1] = r3;
            }
            #pragma unroll
            for (int i = 0; i < 4; i++)
                #pragma unroll
                for (int j = 0; j < 4; j++)
                    mma_f16(&acc[i][j][0], &af[i][0], &bfr[j][0]);
        }
    }

    if (EPI == 1) {
        // Epilogue: sigmoid / log / beta_x (precise exp/log, fp16 outputs)
        const float ab = sc1[0];
        const float bscale = sc2[0];
        #pragma unroll
        for (int i = 0; i < 4; i++) {
            #pragma unroll
            for (int j = 0; j < 4; j++) {
                const int col = n0 + wn + j*8 + thr*2;
                const float b0 = __ldg(bias + col);
                const float b1 = __ldg(bias + col + 1);
                #pragma unroll
                for (int h = 0; h < 2; h++) {
                    const int row = m0 + wm + i*16 + grp + h*8;
                    const float z0 = acc[i][j][2*h+0] + b0 + ab;
                    const float z1 = acc[i][j][2*h+1] + b1 + ab;
                    const float a0 = 1.0f / (1.0f + expf(-z0));
                    const float a1 = 1.0f / (1.0f + expf(-z1));
                    const float2 xn = __half22float2(*(const __half2*)(XrefH + (size_t)row*DN + col));
                    const float la0 = logf(a0 + 1e-8f);
                    const float la1 = logf(a1 + 1e-8f);
                    const float bx0 = bscale * (1.0f - a0) * xn.x;
                    const float bx1 = bscale * (1.0f - a1) * xn.y;
                    *(__half2*)(H1 + (size_t)row*DN + col) = __floats2half2_rn(la0, la1);
                    *(__half2*)(H2 + (size_t)row*DN + col) = __floats2half2_rn(bx0, bx1);
                }
            }
        }
    } else {
        // Epilogue: z = acc * r[row] + bias; tanh*0.05 + residual
        #pragma unroll
        for (int i = 0; i < 4; i++) {
            #pragma unroll
            for (int j = 0; j < 4; j++) {
                const int col = n0 + wn + j*8 + thr*2;
                const float b0 = __ldg(bias + col);
                const float b1 = __ldg(bias + col + 1);
                #pragma unroll
                for (int h = 0; h < 2; h++) {
                    const int row = m0 + wm + i*16 + grp + h*8;
                    const float r = __ldg(rowsc + row);
                    const float g0 = tanhf(acc[i][j][2*h+0] * r + b0);
                    const float g1 = tanhf(acc[i][j][2*h+1] * r + b1);
                    const float2 res = *(const float2*)(XrefF + (size_t)row*DN + col);
                    float2 o;
                    o.x = g0 * 0.05f + res.x;
                    o.y = g1 * 0.05f + res.y;
                    *(float2*)(O + (size_t)row*DN + col) = o;
                }
            }
        }
    }
}

// ---------------------------------------------------------------------------
// Scan phase 1: per (b, seg, channel-pair): segment sums (fp16 in, f32 accum)
// ---------------------------------------------------------------------------
__global__ __launch_bounds__(256) void scan_seg1(
    const __half* __restrict__ la, const __half* __restrict__ bx,
    float* __restrict__ segL, float* __restrict__ segP)
{
    const int d2 = blockIdx.x * 256 + threadIdx.x;
    const int s  = blockIdx.y;
    const int b  = blockIdx.z;
    size_t idx = (size_t)(b*TN + s*SEG) * DN + d2*2;
    float L0 = 0.f, L1 = 0.f, P0 = 0.f, P1 = 0.f;
    #pragma unroll 8
    for (int t = 0; t < SEG; t++) {
        const float2 l = __half22float2(*(const __half2*)(la + idx));
        const float2 x = __half22float2(*(const __half2*)(bx + idx));
        L0 += l.x;  L1 += l.y;
        P0 += x.x * __expf(L0);
        P1 += x.y * __expf(L1);
        idx += DN;
    }
    const size_t o = (size_t)(b*NSEG + s) * DN + d2*2;
    *(float2*)(segL + o) = make_float2(L0, L1);
    *(float2*)(segP + o) = make_float2(P0, P1);
}

// ---------------------------------------------------------------------------
// Scan phase 2: per (b, d): exclusive combine across NSEG segments.
// m = log_alpha[b, t=0, d] (cumsum non-increasing -> max at first element).
// ---------------------------------------------------------------------------
__global__ __launch_bounds__(256) void scan_seg2(
    const __half* __restrict__ la,
    const float* __restrict__ segL, const float* __restrict__ segP,
    float* __restrict__ Lb, float* __restrict__ sb)
{
    const int idx = blockIdx.x * 256 + threadIdx.x;   // 0..4095
    const int b = idx >> 10;
    const int d = idx & (DN - 1);
    const float m = __half2float(la[(size_t)b * TN * DN + d]);
    float Lex = 0.f, ss = 0.f;
    #pragma unroll
    for (int s = 0; s < NSEG; s++) {
        const size_t o = (size_t)(b*NSEG + s) * DN + d;
        Lb[o] = Lex - m;
        sb[o] = ss;
        ss  += segP[o] * __expf(Lex - m);
        Lex += segL[o];
    }
}

// ---------------------------------------------------------------------------
// Scan phase 3: final streaming pass; raw f32 output.
// ---------------------------------------------------------------------------
__global__ __launch_bounds__(256) void scan_seg3(
    const __half* __restrict__ la, const __half* __restrict__ bx,
    const float* __restrict__ Lb, const float* __restrict__ sb,
    float* __restrict__ out)
{
    const int d2 = blockIdx.x * 256 + threadIdx.x;
    const int s  = blockIdx.y;
    const int b  = blockIdx.z;
    const size_t o = (size_t)(b*NSEG + s) * DN + d2*2;
    const float2 Lb2 = *(const float2*)(Lb + o);
    const float2 sb2 = *(const float2*)(sb + o);
    float L0 = Lb2.x, L1 = Lb2.y;
    float s0 = sb2.x, s1 = sb2.y;
    size_t idx = (size_t)(b*TN + s*SEG) * DN + d2*2;
    #pragma unroll 8
    for (int t = 0; t < SEG; t++) {
        const float2 l = __half22float2(*(const __half2*)(la + idx));
        const float2 x = __half22float2(*(const __half2*)(bx + idx));
        L0 += l.x;  L1 += l.y;
        const float c0 = __expf(L0);
        const float c1 = __expf(L1);
        s0 += x.x * c0;
        s1 += x.y * c1;
        *(float2*)(out + idx) = make_float2(s0 / (c0 + 1e-8f), s1 / (c1 + 1e-8f));
        idx += DN;
    }
}

// ---------------------------------------------------------------------------
// Rowscale: per row compute r = max|out|, write r and fp16 out/r.
// One warp per row; 8 rows per block.
// ---------------------------------------------------------------------------
__global__ __launch_bounds__(256) void rowscale_kernel(
    const float* __restrict__ in, float* __restrict__ rmax,
    __half* __restrict__ outh)
{
    const int warp = threadIdx.x >> 5;
    const int lane = threadIdx.x & 31;
    const int row  = blockIdx.x * 8 + warp;

    const float4* rp = (const float4*)(in + (size_t)row * DN);
    float mx = 0.f;
    #pragma unroll
    for (int i = 0; i < 8; i++) {
        const float4 v = rp[lane + 32*i];
        mx = fmaxf(mx, fmaxf(fmaxf(fabsf(v.x), fabsf(v.y)),
                             fmaxf(fabsf(v.z), fabsf(v.w))));
    }
    #pragma unroll
    for (int o = 16; o > 0; o >>= 1)
        mx = fmaxf(mx, __shfl_xor_sync(0xffffffffu, mx, o));
    mx = fmaxf(mx, 1e-30f);
    if (lane == 0) rmax[row] = mx;
    const float inv = 1.0f / mx;

    #pragma unroll
    for (int i = 0; i < 8; i++) {
        const int c = lane + 32*i;
        const float4 v = rp[c];
        __half2 h01 = __floats2half2_rn(v.x * inv, v.y * inv);
        __half2 h23 = __floats2half2_rn(v.z * inv, v.w * inv);
        uint2 pk;
        pk.x = *(uint32_t*)&h01;
        pk.y = *(uint32_t*)&h23;
        *(uint2*)(outh + (size_t)row * DN + c*4) = pk;
    }
}

// ---------------------------------------------------------------------------
// Launch
// ---------------------------------------------------------------------------
extern "C" void kernel_launch(void* const* d_in, const int* in_sizes, int n_in,
                              void* d_out, int out_size)
{
    const float* x    = (const float*)d_in[0];
    const float* ln_w = (const float*)d_in[1];
    const float* ln_b = (const float*)d_in[2];
    const float* Wf   = (const float*)d_in[3];
    const float* bf   = (const float*)d_in[4];
    const float* Wr   = (const float*)d_in[5];
    const float* br   = (const float*)d_in[6];
    const float* ab   = (const float*)d_in[7];
    const float* bs   = (const float*)d_in[8];
    float* out = (float*)d_out;

    float *p_scan, *p_rmax, *p_segL, *p_segP, *p_Lb, *p_sb;
    __half *p_xnorm, *p_la, *p_bx, *p_wf, *p_wrh, *p_scanh;
    cudaGetSymbolAddress((void**)&p_xnorm, g_xnorm);
    cudaGetSymbolAddress((void**)&p_la,    g_la);
    cudaGetSymbolAddress((void**)&p_bx,    g_bx);
    cudaGetSymbolAddress((void**)&p_scan,  g_scan);
    cudaGetSymbolAddress((void**)&p_scanh, g_scanh);
    cudaGetSymbolAddress((void**)&p_rmax,  g_rmax);
    cudaGetSymbolAddress((void**)&p_wf,    g_wf);
    cudaGetSymbolAddress((void**)&p_wrh,   g_wrh);
    cudaGetSymbolAddress((void**)&p_segL,  g_segL);
    cudaGetSymbolAddress((void**)&p_segP,  g_segP);
    cudaGetSymbolAddress((void**)&p_Lb,    g_Lb);
    cudaGetSymbolAddress((void**)&p_sb,    g_sb);

    cudaFuncSetAttribute(gemm_h<1>, cudaFuncAttributeMaxDynamicSharedMemorySize, GEMMH_SMEM);
    cudaFuncSetAttribute(gemm_h<2>, cudaFuncAttributeMaxDynamicSharedMemorySize, GEMMH_SMEM);

    // 0) Weight conversions (~6us total)
    cvt_h_kernel<<<(DN*DN/4)/256, 256>>>(Wf, p_wf);
    cvt_h_kernel<<<(DN*DN/4)/256, 256>>>(Wr, p_wrh);

    // 1) LayerNorm (warp-per-row, fp16 output)
    ln_kernel<<<MN/8, 256>>>(x, ln_w, ln_b, p_xnorm);

    // 2) GEMM1 (fp16 + ldmatrix, 4-stage ring, unrolled, 2 CTAs/SM)
    dim3 ggrid(DN/128, MN/128);
    gemm_h<1><<<ggrid, 256, GEMMH_SMEM>>>(
        p_xnorm, p_wf, bf, ab, bs, p_xnorm, nullptr, nullptr,
        p_la, p_bx, nullptr);

    // 3) Segmented scan over T (SEG=64, fp16 streams, f32 accumulation)
    dim3 sgrid(DN/512, NSEG, BZ);
    scan_seg1<<<sgrid, 256>>>(p_la, p_bx, p_segL, p_segP);
    scan_seg2<<<(BZ*DN)/256, 256>>>(p_la, p_segL, p_segP, p_Lb, p_sb);
    scan_seg3<<<sgrid, 256>>>(p_la, p_bx, p_Lb, p_sb, p_scan);

    // 3b) Per-row scale + fp16 conversion of scan output
    rowscale_kernel<<<MN/8, 256>>>(p_scan, p_rmax, p_scanh);

    // 4) GEMM2 (fp16 + ldmatrix, row-rescaled): tanh(scan @ Wr^T + br)*0.05 + x
    gemm_h<2><<<ggrid, 256, GEMMH_SMEM>>>(
        p_scanh, p_wrh, br, nullptr, nullptr, nullptr, x, p_rmax,
        nullptr, nullptr, out);
}

// round 12
// speedup vs baseline: 1.1840x; 1.0864x over previous
#include <cuda_runtime.h>
#include <cuda_fp16.h>
#include <cstdint>

// Problem constants (fixed shapes)
#define BZ 4
#define TN 4096
#define DN 1024
#define MN (BZ*TN)        // 16384 rows
#define SEG 64
#define NSEG (TN/SEG)     // 64

// ---------------------------------------------------------------------------
// Scratch (static __device__ arrays; no allocation allowed)
// ---------------------------------------------------------------------------
__device__ __half g_xnorm[(size_t)MN*DN];   // fp16 LN output
__device__ __half g_la   [(size_t)MN*DN];   // fp16 log_alpha
__device__ __half g_bx   [(size_t)MN*DN];   // fp16 beta_x
__device__ float  g_scan [(size_t)MN*DN];   // f32 scan output
__device__ __half g_scanh[(size_t)MN*DN];   // fp16 row-scaled scan output
__device__ float  g_rmax [MN];              // per-row scale
__device__ __half g_wf   [(size_t)DN*DN];   // fp16 Wf
__device__ __half g_wrh  [(size_t)DN*DN];   // fp16 Wr
__device__ float  g_segL[BZ*NSEG*DN];
__device__ float  g_segP[BZ*NSEG*DN];
__device__ float  g_Lb  [BZ*NSEG*DN];
__device__ float  g_sb  [BZ*NSEG*DN];

// ---------------------------------------------------------------------------
// Helpers
// ---------------------------------------------------------------------------
__device__ __forceinline__ void cp16s(uint32_t s, const void* g) {
    asm volatile("cp.async.cg.shared.global [%0], [%1], 16;\n" :: "r"(s), "l"(g));
}
__device__ __forceinline__ void cp_commit() {
    asm volatile("cp.async.commit_group;\n");
}
__device__ __forceinline__ void ldsm4(uint32_t& r0, uint32_t& r1, uint32_t& r2,
                                      uint32_t& r3, uint32_t addr) {
    asm volatile("ldmatrix.sync.aligned.m8n8.x4.shared.b16 {%0,%1,%2,%3}, [%4];\n"
                 : "=r"(r0), "=r"(r1), "=r"(r2), "=r"(r3) : "r"(addr));
}
__device__ __forceinline__ void mma_f16(float* c, const uint32_t* a, const uint32_t* b) {
    asm volatile(
        "mma.sync.aligned.m16n8k16.row.col.f32.f16.f16.f32 "
        "{%0,%1,%2,%3}, {%4,%5,%6,%7}, {%8,%9}, {%0,%1,%2,%3};\n"
        : "+f"(c[0]), "+f"(c[1]), "+f"(c[2]), "+f"(c[3])
        : "r"(a[0]), "r"(a[1]), "r"(a[2]), "r"(a[3]),
          "r"(b[0]), "r"(b[1]));
}

// ---------------------------------------------------------------------------
// Kernel 0: convert f32 weight matrix to fp16
// ---------------------------------------------------------------------------
__global__ __launch_bounds__(256) void cvt_h_kernel(
    const float* __restrict__ in, __half* __restrict__ out)
{
    const int i = blockIdx.x * 256 + threadIdx.x;
    const float4 v = ((const float4*)in)[i];
    __half2 h01 = __floats2half2_rn(v.x, v.y);
    __half2 h23 = __floats2half2_rn(v.z, v.w);
    uint2 pk;
    pk.x = *(uint32_t*)&h01;
    pk.y = *(uint32_t*)&h23;
    *(uint2*)(out + (size_t)i * 4) = pk;
}

// ---------------------------------------------------------------------------
// Kernel 1: LayerNorm, one WARP per row, fp16 output.
// ---------------------------------------------------------------------------
__global__ __launch_bounds__(256) void ln_kernel(
    const float* __restrict__ x, const float* __restrict__ w,
    const float* __restrict__ b, __half* __restrict__ y)
{
    const int warp = threadIdx.x >> 5;
    const int lane = threadIdx.x & 31;
    const int row  = blockIdx.x * 8 + warp;

    const float4* xr = (const float4*)(x + (size_t)row * DN);

    float s = 0.f;
    #pragma unroll
    for (int i = 0; i < 8; i++) {
        const float4 v = xr[lane + 32*i];
        s += (v.x + v.y) + (v.z + v.w);
    }
    #pragma unroll
    for (int o = 16; o > 0; o >>= 1) s += __shfl_xor_sync(0xffffffffu, s, o);
    const float mu = s * (1.0f / DN);

    float s2 = 0.f;
    #pragma unroll
    for (int i = 0; i < 8; i++) {
        const float4 v = xr[lane + 32*i];
        const float d0 = v.x - mu, d1 = v.y - mu, d2 = v.z - mu, d3 = v.w - mu;
        s2 += (d0*d0 + d1*d1) + (d2*d2 + d3*d3);
    }
    #pragma unroll
    for (int o = 16; o > 0; o >>= 1) s2 += __shfl_xor_sync(0xffffffffu, s2, o);
    const float rs = rsqrtf(s2 * (1.0f / DN) + 1e-5f);

    const float4* wv = (const float4*)w;
    const float4* bv = (const float4*)b;
    #pragma unroll
    for (int i = 0; i < 8; i++) {
        const int c = lane + 32*i;
        const float4 v  = xr[c];
        const float4 w4 = wv[c];
        const float4 b4 = bv[c];
        __half2 h01 = __floats2half2_rn((v.x - mu) * rs * w4.x + b4.x,
                                        (v.y - mu) * rs * w4.y + b4.y);
        __half2 h23 = __floats2half2_rn((v.z - mu) * rs * w4.z + b4.z,
                                        (v.w - mu) * rs * w4.w + b4.w);
        uint2 pk;
        pk.x = *(uint32_t*)&h01;
        pk.y = *(uint32_t*)&h23;
        *(uint2*)(y + (size_t)row * DN + c*4) = pk;
    }
}

// ---------------------------------------------------------------------------
// fp16 GEMM: C[m,n] = sum_k A[m,k]*W[n,k], fp16 in, f32 accum.
// 128x128 CTA tile, 512 threads (16 warps, 32x32 warp tile), BK=32,
// 4-stage cp.async ring, ldmatrix fragments. 2 CTAs/SM -> 32 warps/SM.
// EPI==1: sigmoid/log_alpha/beta_x epilogue (fp16 out).
// EPI==2: per-row-rescale + tanh*0.05 + residual (f32 out).
// ---------------------------------------------------------------------------
#define RS1 40                       // smem row stride in halves (80B)
#define STAGE1_H (128*RS1)           // halves per operand per stage
#define STG_BYTES (2*STAGE1_H*2)     // A+B bytes per stage = 20480
#define NST 4
#define GEMMH_SMEM (NST*STG_BYTES)   // 81920 (2 CTAs/SM)

template<int EPI>
__global__ __launch_bounds__(512, 2) void gemm_h(
    const __half* __restrict__ A, const __half* __restrict__ W,
    const float* __restrict__ bias,
    const float* __restrict__ sc1,    // alpha_bias (EPI==1)
    const float* __restrict__ sc2,    // beta_scale (EPI==1)
    const __half* __restrict__ XrefH, // x_norm fp16 (EPI==1)
    const float* __restrict__ XrefF,  // residual x (EPI==2)
    const float* __restrict__ rowsc,  // per-row scale (EPI==2)
    __half* __restrict__ H1,          // log_alpha (EPI==1)
    __half* __restrict__ H2,          // beta_x (EPI==1)
    float*  __restrict__ O)           // final out (EPI==2)
{
    extern __shared__ char dynsm[];
    const uint32_t smem_u = (uint32_t)__cvta_generic_to_shared(dynsm);

    const int tid  = threadIdx.x;
    const int m0   = blockIdx.y * 128;
    const int n0   = blockIdx.x * 128;
    const int lane = tid & 31;
    const int warp = tid >> 5;             // 0..15
    const int wm   = (warp & 3) * 32;      // 4 m-strips of 32
    const int wn   = (warp >> 2) * 32;     // 4 n-strips of 32
    const int grp  = lane >> 2;
    const int thr  = lane & 3;

    float acc[2][4][4];
    #pragma unroll
    for (int i = 0; i < 2; i++)
        #pragma unroll
        for (int j = 0; j < 4; j++)
            #pragma unroll
            for (int r = 0; r < 4; r++) acc[i][j][r] = 0.f;

    const int KT = DN / 32;
    const int lr = tid >> 2;            // row 0..127
    const int lc = (tid & 3) * 8;       // half offset (0,8,16,24)

    // cp.async destinations; each thread does ONE A chunk + ONE B chunk
    const uint32_t awr = smem_u + (uint32_t)((lr*RS1 + lc) * 2);
    const uint32_t bwr = awr + (uint32_t)(STAGE1_H * 2);
    const __half* Arow = A + (size_t)(m0 + lr) * DN + lc;
    const __half* Wrow = W + (size_t)(n0 + lr) * DN + lc;

    // Per-lane ldmatrix base addresses (stage 0)
    const int arow  = lane & 15;
    const int koff8 = (lane >> 4) * 8;
    uint32_t aB[2], bB[2];
    #pragma unroll
    for (int i = 0; i < 2; i++)
        aB[i] = smem_u + (uint32_t)(((wm + i*16 + arow)*RS1 + koff8) * 2);
    #pragma unroll
    for (int jj = 0; jj < 2; jj++)
        bB[jj] = smem_u + (uint32_t)(STAGE1_H*2 + ((wn + jj*16 + arow)*RS1 + koff8) * 2);

    auto issue = [&](int kt) {
        const uint32_t buf = (uint32_t)(kt & 3) * STG_BYTES;
        cp16s(awr + buf, Arow + kt * 32);
        cp16s(bwr + buf, Wrow + kt * 32);
        cp_commit();
    };

    issue(0);
    issue(1);
    issue(2);

    #pragma unroll 4
    for (int kt = 0; kt < KT; ++kt) {
        if (kt + 3 < KT) asm volatile("cp.async.wait_group 2;\n");
        else             asm volatile("cp.async.wait_group 0;\n");
        __syncthreads();
        if (kt + 3 < KT) issue(kt + 3);

        const uint32_t stg = (uint32_t)((kt & 3) * STG_BYTES);

        #pragma unroll
        for (int ks = 0; ks < 2; ks++) {
            uint32_t af[2][4];
            uint32_t bfr[4][2];
            #pragma unroll
            for (int i = 0; i < 2; i++)
                ldsm4(af[i][0], af[i][1], af[i][2], af[i][3],
                      aB[i] + stg + ks*32);
            #pragma unroll
            for (int jj = 0; jj < 2; jj++) {
                uint32_t r0, r1, r2, r3;
                ldsm4(r0, r1, r2, r3, bB[jj] + stg + ks*32);
                bfr[2*jj][0]   = r0;
                bfr[2*jj+1][0] = r1;
                bfr[2*jj][1]   = r2;
                bfr[2*jj+1][1] = r3;
            }
            #pragma unroll
            for (int i = 0; i < 2; i++)
                #pragma unroll
                for (int j = 0; j < 4; j++)
                    mma_f16(&acc[i][j][0], &af[i][0], &bfr[j][0]);
        }
    }

    if (EPI == 1) {
        // Epilogue: sigmoid / log / beta_x (precise exp/log, fp16 outputs)
        const float ab = sc1[0];
        const float bscale = sc2[0];
        #pragma unroll
        for (int i = 0; i < 2; i++) {
            #pragma unroll
            for (int j = 0; j < 4; j++) {
                const int col = n0 + wn + j*8 + thr*2;
                const float b0 = __ldg(bias + col);
                const float b1 = __ldg(bias + col + 1);
                #pragma unroll
                for (int h = 0; h < 2; h++) {
                    const int row = m0 + wm + i*16 + grp + h*8;
                    const float z0 = acc[i][j][2*h+0] + b0 + ab;
                    const float z1 = acc[i][j][2*h+1] + b1 + ab;
                    const float a0 = 1.0f / (1.0f + expf(-z0));
                    const float a1 = 1.0f / (1.0f + expf(-z1));
                    const float2 xn = __half22float2(*(const __half2*)(XrefH + (size_t)row*DN + col));
                    const float la0 = logf(a0 + 1e-8f);
                    const float la1 = logf(a1 + 1e-8f);
                    const float bx0 = bscale * (1.0f - a0) * xn.x;
                    const float bx1 = bscale * (1.0f - a1) * xn.y;
                    *(__half2*)(H1 + (size_t)row*DN + col) = __floats2half2_rn(la0, la1);
                    *(__half2*)(H2 + (size_t)row*DN + col) = __floats2half2_rn(bx0, bx1);
                }
            }
        }
    } else {
        // Epilogue: z = acc * r[row] + bias; tanh*0.05 + residual
        #pragma unroll
        for (int i = 0; i < 2; i++) {
            #pragma unroll
            for (int j = 0; j < 4; j++) {
                const int col = n0 + wn + j*8 + thr*2;
                const float b0 = __ldg(bias + col);
                const float b1 = __ldg(bias + col + 1);
                #pragma unroll
                for (int h = 0; h < 2; h++) {
                    const int row = m0 + wm + i*16 + grp + h*8;
                    const float r = __ldg(rowsc + row);
                    const float g0 = tanhf(acc[i][j][2*h+0] * r + b0);
                    const float g1 = tanhf(acc[i][j][2*h+1] * r + b1);
                    const float2 res = *(const float2*)(XrefF + (size_t)row*DN + col);
                    float2 o;
                    o.x = g0 * 0.05f + res.x;
                    o.y = g1 * 0.05f + res.y;
                    *(float2*)(O + (size_t)row*DN + col) = o;
                }
            }
        }
    }
}

// ---------------------------------------------------------------------------
// Scan phase 1: per (b, seg, channel-pair): segment sums (fp16 in, f32 accum)
// ---------------------------------------------------------------------------
__global__ __launch_bounds__(256) void scan_seg1(
    const __half* __restrict__ la, const __half* __restrict__ bx,
    float* __restrict__ segL, float* __restrict__ segP)
{
    const int d2 = blockIdx.x * 256 + threadIdx.x;
    const int s  = blockIdx.y;
    const int b  = blockIdx.z;
    size_t idx = (size_t)(b*TN + s*SEG) * DN + d2*2;
    float L0 = 0.f, L1 = 0.f, P0 = 0.f, P1 = 0.f;
    #pragma unroll 8
    for (int t = 0; t < SEG; t++) {
        const float2 l = __half22float2(*(const __half2*)(la + idx));
        const float2 x = __half22float2(*(const __half2*)(bx + idx));
        L0 += l.x;  L1 += l.y;
        P0 += x.x * __expf(L0);
        P1 += x.y * __expf(L1);
        idx += DN;
    }
    const size_t o = (size_t)(b*NSEG + s) * DN + d2*2;
    *(float2*)(segL + o) = make_float2(L0, L1);
    *(float2*)(segP + o) = make_float2(P0, P1);
}

// ---------------------------------------------------------------------------
// Scan phase 2: per (b, d): exclusive combine across NSEG segments.
// m = log_alpha[b, t=0, d] (cumsum non-increasing -> max at first element).
// ---------------------------------------------------------------------------
__global__ __launch_bounds__(256) void scan_seg2(
    const __half* __restrict__ la,
    const float* __restrict__ segL, const float* __restrict__ segP,
    float* __restrict__ Lb, float* __restrict__ sb)
{
    const int idx = blockIdx.x * 256 + threadIdx.x;   // 0..4095
    const int b = idx >> 10;
    const int d = idx & (DN - 1);
    const float m = __half2float(la[(size_t)b * TN * DN + d]);
    float Lex = 0.f, ss = 0.f;
    #pragma unroll
    for (int s = 0; s < NSEG; s++) {
        const size_t o = (size_t)(b*NSEG + s) * DN + d;
        Lb[o] = Lex - m;
        sb[o] = ss;
        ss  += segP[o] * __expf(Lex - m);
        Lex += segL[o];
    }
}

// ---------------------------------------------------------------------------
// Scan phase 3: final streaming pass; raw f32 output.
// ---------------------------------------------------------------------------
__global__ __launch_bounds__(256) void scan_seg3(
    const __half* __restrict__ la, const __half* __restrict__ bx,
    const float* __restrict__ Lb, const float* __restrict__ sb,
    float* __restrict__ out)
{
    const int d2 = blockIdx.x * 256 + threadIdx.x;
    const int s  = blockIdx.y;
    const int b  = blockIdx.z;
    const size_t o = (size_t)(b*NSEG + s) * DN + d2*2;
    const float2 Lb2 = *(const float2*)(Lb + o);
    const float2 sb2 = *(const float2*)(sb + o);
    float L0 = Lb2.x, L1 = Lb2.y;
    float s0 = sb2.x, s1 = sb2.y;
    size_t idx = (size_t)(b*TN + s*SEG) * DN + d2*2;
    #pragma unroll 8
    for (int t = 0; t < SEG; t++) {
        const float2 l = __half22float2(*(const __half2*)(la + idx));
        const float2 x = __half22float2(*(const __half2*)(bx + idx));
        L0 += l.x;  L1 += l.y;
        const float c0 = __expf(L0);
        const float c1 = __expf(L1);
        s0 += x.x * c0;
        s1 += x.y * c1;
        *(float2*)(out + idx) = make_float2(s0 / (c0 + 1e-8f), s1 / (c1 + 1e-8f));
        idx += DN;
    }
}

// ---------------------------------------------------------------------------
// Rowscale: per row compute r = max|out|, write r and fp16 out/r.
// One warp per row; 8 rows per block.
// ---------------------------------------------------------------------------
__global__ __launch_bounds__(256) void rowscale_kernel(
    const float* __restrict__ in, float* __restrict__ rmax,
    __half* __restrict__ outh)
{
    const int warp = threadIdx.x >> 5;
    const int lane = threadIdx.x & 31;
    const int row  = blockIdx.x * 8 + warp;

    const float4* rp = (const float4*)(in + (size_t)row * DN);
    float mx = 0.f;
    #pragma unroll
    for (int i = 0; i < 8; i++) {
        const float4 v = rp[lane + 32*i];
        mx = fmaxf(mx, fmaxf(fmaxf(fabsf(v.x), fabsf(v.y)),
                             fmaxf(fabsf(v.z), fabsf(v.w))));
    }
    #pragma unroll
    for (int o = 16; o > 0; o >>= 1)
        mx = fmaxf(mx, __shfl_xor_sync(0xffffffffu, mx, o));
    mx = fmaxf(mx, 1e-30f);
    if (lane == 0) rmax[row] = mx;
    const float inv = 1.0f / mx;

    #pragma unroll
    for (int i = 0; i < 8; i++) {
        const int c = lane + 32*i;
        const float4 v = rp[c];
        __half2 h01 = __floats2half2_rn(v.x * inv, v.y * inv);
        __half2 h23 = __floats2half2_rn(v.z * inv, v.w * inv);
        uint2 pk;
        pk.x = *(uint32_t*)&h01;
        pk.y = *(uint32_t*)&h23;
        *(uint2*)(outh + (size_t)row * DN + c*4) = pk;
    }
}

// ---------------------------------------------------------------------------
// Launch
// ---------------------------------------------------------------------------
extern "C" void kernel_launch(void* const* d_in, const int* in_sizes, int n_in,
                              void* d_out, int out_size)
{
    const float* x    = (const float*)d_in[0];
    const float* ln_w = (const float*)d_in[1];
    const float* ln_b = (const float*)d_in[2];
    const float* Wf   = (const float*)d_in[3];
    const float* bf   = (const float*)d_in[4];
    const float* Wr   = (const float*)d_in[5];
    const float* br   = (const float*)d_in[6];
    const float* ab   = (const float*)d_in[7];
    const float* bs   = (const float*)d_in[8];
    float* out = (float*)d_out;

    float *p_scan, *p_rmax, *p_segL, *p_segP, *p_Lb, *p_sb;
    __half *p_xnorm, *p_la, *p_bx, *p_wf, *p_wrh, *p_scanh;
    cudaGetSymbolAddress((void**)&p_xnorm, g_xnorm);
    cudaGetSymbolAddress((void**)&p_la,    g_la);
    cudaGetSymbolAddress((void**)&p_bx,    g_bx);
    cudaGetSymbolAddress((void**)&p_scan,  g_scan);
    cudaGetSymbolAddress((void**)&p_scanh, g_scanh);
    cudaGetSymbolAddress((void**)&p_rmax,  g_rmax);
    cudaGetSymbolAddress((void**)&p_wf,    g_wf);
    cudaGetSymbolAddress((void**)&p_wrh,   g_wrh);
    cudaGetSymbolAddress((void**)&p_segL,  g_segL);
    cudaGetSymbolAddress((void**)&p_segP,  g_segP);
    cudaGetSymbolAddress((void**)&p_Lb,    g_Lb);
    cudaGetSymbolAddress((void**)&p_sb,    g_sb);

    cudaFuncSetAttribute(gemm_h<1>, cudaFuncAttributeMaxDynamicSharedMemorySize, GEMMH_SMEM);
    cudaFuncSetAttribute(gemm_h<2>, cudaFuncAttributeMaxDynamicSharedMemorySize, GEMMH_SMEM);

    // 0) Weight conversions (~6us total)
    cvt_h_kernel<<<(DN*DN/4)/256, 256>>>(Wf, p_wf);
    cvt_h_kernel<<<(DN*DN/4)/256, 256>>>(Wr, p_wrh);

    // 1) LayerNorm (warp-per-row, fp16 output)
    ln_kernel<<<MN/8, 256>>>(x, ln_w, ln_b, p_xnorm);

    // 2) GEMM1 (fp16, 512 thr, 32x32 warp tiles, 32 warps/SM): fused epilogue
    dim3 ggrid(DN/128, MN/128);
    gemm_h<1><<<ggrid, 512, GEMMH_SMEM>>>(
        p_xnorm, p_wf, bf, ab, bs, p_xnorm, nullptr, nullptr,
        p_la, p_bx, nullptr);

    // 3) Segmented scan over T (SEG=64, fp16 streams, f32 accumulation)
    dim3 sgrid(DN/512, NSEG, BZ);
    scan_seg1<<<sgrid, 256>>>(p_la, p_bx, p_segL, p_segP);
    scan_seg2<<<(BZ*DN)/256, 256>>>(p_la, p_segL, p_segP, p_Lb, p_sb);
    scan_seg3<<<sgrid, 256>>>(p_la, p_bx, p_Lb, p_sb, p_scan);

    // 3b) Per-row scale + fp16 conversion of scan output
    rowscale_kernel<<<MN/8, 256>>>(p_scan, p_rmax, p_scanh);

    // 4) GEMM2 (fp16, row-rescaled): tanh(scan @ Wr^T + br)*0.05 + x
    gemm_h<2><<<ggrid, 512, GEMMH_SMEM>>>(
        p_scanh, p_wrh, br, nullptr, nullptr, nullptr, x, p_rmax,
        nullptr, nullptr, out);
}

// round 13
// speedup vs baseline: 1.1841x; 1.0001x over previous
#include <cuda_runtime.h>
#include <cuda_fp16.h>
#include <cstdint>

// Problem constants (fixed shapes)
#define BZ 4
#define TN 4096
#define DN 1024
#define MN (BZ*TN)        // 16384 rows
#define SEG 64
#define NSEG (TN/SEG)     // 64

// ---------------------------------------------------------------------------
// Scratch (static __device__ arrays; no allocation allowed)
// ---------------------------------------------------------------------------
__device__ __half g_xnorm[(size_t)MN*DN];   // fp16 LN output
__device__ __half g_la   [(size_t)MN*DN];   // fp16 log_alpha
__device__ __half g_bx   [(size_t)MN*DN];   // fp16 beta_x
__device__ __half g_scanh[(size_t)MN*DN];   // fp16 row-scaled scan output
__device__ float  g_rmax [MN];              // per-row scale
__device__ __half g_wf   [(size_t)DN*DN];   // fp16 Wf
__device__ __half g_wrh  [(size_t)DN*DN];   // fp16 Wr
__device__ float  g_segL[BZ*NSEG*DN];
__device__ float  g_segP[BZ*NSEG*DN];
__device__ float  g_Lb  [BZ*NSEG*DN];
__device__ float  g_sb  [BZ*NSEG*DN];

// ---------------------------------------------------------------------------
// Helpers
// ---------------------------------------------------------------------------
__device__ __forceinline__ void cp16s(uint32_t s, const void* g) {
    asm volatile("cp.async.cg.shared.global [%0], [%1], 16;\n" :: "r"(s), "l"(g));
}
__device__ __forceinline__ void cp_commit() {
    asm volatile("cp.async.commit_group;\n");
}
__device__ __forceinline__ void ldsm4(uint32_t& r0, uint32_t& r1, uint32_t& r2,
                                      uint32_t& r3, uint32_t addr) {
    asm volatile("ldmatrix.sync.aligned.m8n8.x4.shared.b16 {%0,%1,%2,%3}, [%4];\n"
                 : "=r"(r0), "=r"(r1), "=r"(r2), "=r"(r3) : "r"(addr));
}
__device__ __forceinline__ void mma_f16(float* c, const uint32_t* a, const uint32_t* b) {
    asm volatile(
        "mma.sync.aligned.m16n8k16.row.col.f32.f16.f16.f32 "
        "{%0,%1,%2,%3}, {%4,%5,%6,%7}, {%8,%9}, {%0,%1,%2,%3};\n"
        : "+f"(c[0]), "+f"(c[1]), "+f"(c[2]), "+f"(c[3])
        : "r"(a[0]), "r"(a[1]), "r"(a[2]), "r"(a[3]),
          "r"(b[0]), "r"(b[1]));
}
__device__ __forceinline__ float fast_tanh(float x) {
    float y; asm("tanh.approx.f32 %0, %1;" : "=f"(y) : "f"(x)); return y;
}

// ---------------------------------------------------------------------------
// Kernel 0: convert f32 weight matrix to fp16
// ---------------------------------------------------------------------------
__global__ __launch_bounds__(256) void cvt_h_kernel(
    const float* __restrict__ in, __half* __restrict__ out)
{
    const int i = blockIdx.x * 256 + threadIdx.x;
    const float4 v = ((const float4*)in)[i];
    __half2 h01 = __floats2half2_rn(v.x, v.y);
    __half2 h23 = __floats2half2_rn(v.z, v.w);
    uint2 pk;
    pk.x = *(uint32_t*)&h01;
    pk.y = *(uint32_t*)&h23;
    *(uint2*)(out + (size_t)i * 4) = pk;
}

// ---------------------------------------------------------------------------
// Kernel 1: LayerNorm, one WARP per row, fp16 output.
// ---------------------------------------------------------------------------
__global__ __launch_bounds__(256) void ln_kernel(
    const float* __restrict__ x, const float* __restrict__ w,
    const float* __restrict__ b, __half* __restrict__ y)
{
    const int warp = threadIdx.x >> 5;
    const int lane = threadIdx.x & 31;
    const int row  = blockIdx.x * 8 + warp;

    const float4* xr = (const float4*)(x + (size_t)row * DN);

    float s = 0.f;
    #pragma unroll
    for (int i = 0; i < 8; i++) {
        const float4 v = xr[lane + 32*i];
        s += (v.x + v.y) + (v.z + v.w);
    }
    #pragma unroll
    for (int o = 16; o > 0; o >>= 1) s += __shfl_xor_sync(0xffffffffu, s, o);
    const float mu = s * (1.0f / DN);

    float s2 = 0.f;
    #pragma unroll
    for (int i = 0; i < 8; i++) {
        const float4 v = xr[lane + 32*i];
        const float d0 = v.x - mu, d1 = v.y - mu, d2 = v.z - mu, d3 = v.w - mu;
        s2 += (d0*d0 + d1*d1) + (d2*d2 + d3*d3);
    }
    #pragma unroll
    for (int o = 16; o > 0; o >>= 1) s2 += __shfl_xor_sync(0xffffffffu, s2, o);
    const float rs = rsqrtf(s2 * (1.0f / DN) + 1e-5f);

    const float4* wv = (const float4*)w;
    const float4* bv = (const float4*)b;
    #pragma unroll
    for (int i = 0; i < 8; i++) {
        const int c = lane + 32*i;
        const float4 v  = xr[c];
        const float4 w4 = wv[c];
        const float4 b4 = bv[c];
        __half2 h01 = __floats2half2_rn((v.x - mu) * rs * w4.x + b4.x,
                                        (v.y - mu) * rs * w4.y + b4.y);
        __half2 h23 = __floats2half2_rn((v.z - mu) * rs * w4.z + b4.z,
                                        (v.w - mu) * rs * w4.w + b4.w);
        uint2 pk;
        pk.x = *(uint32_t*)&h01;
        pk.y = *(uint32_t*)&h23;
        *(uint2*)(y + (size_t)row * DN + c*4) = pk;
    }
}

// ---------------------------------------------------------------------------
// fp16 GEMM: C[m,n] = sum_k A[m,k]*W[n,k], fp16 in, f32 accum.
// 128x128 CTA tile, 512 threads (16 warps, 32x32 warp tile), BK=32,
// 4-stage cp.async ring, ldmatrix fragments. 2 CTAs/SM -> 32 warps/SM.
// EPI==1: sigmoid/log_alpha/beta_x epilogue (fp16 out).
// EPI==2: per-row-rescale + tanh*0.05 + residual (f32 out).
// ---------------------------------------------------------------------------
#define RS1 40                       // smem row stride in halves (80B)
#define STAGE1_H (128*RS1)           // halves per operand per stage
#define STG_BYTES (2*STAGE1_H*2)     // A+B bytes per stage = 20480
#define NST 4
#define GEMMH_SMEM (NST*STG_BYTES)   // 81920 (2 CTAs/SM)

template<int EPI>
__global__ __launch_bounds__(512, 2) void gemm_h(
    const __half* __restrict__ A, const __half* __restrict__ W,
    const float* __restrict__ bias,
    const float* __restrict__ sc1,    // alpha_bias (EPI==1)
    const float* __restrict__ sc2,    // beta_scale (EPI==1)
    const __half* __restrict__ XrefH, // x_norm fp16 (EPI==1)
    const float* __restrict__ XrefF,  // residual x (EPI==2)
    const float* __restrict__ rowsc,  // per-row scale (EPI==2)
    __half* __restrict__ H1,          // log_alpha (EPI==1)
    __half* __restrict__ H2,          // beta_x (EPI==1)
    float*  __restrict__ O)           // final out (EPI==2)
{
    extern __shared__ char dynsm[];
    const uint32_t smem_u = (uint32_t)__cvta_generic_to_shared(dynsm);

    const int tid  = threadIdx.x;
    const int m0   = blockIdx.y * 128;
    const int n0   = blockIdx.x * 128;
    const int lane = tid & 31;
    const int warp = tid >> 5;             // 0..15
    const int wm   = (warp & 3) * 32;      // 4 m-strips of 32
    const int wn   = (warp >> 2) * 32;     // 4 n-strips of 32
    const int grp  = lane >> 2;
    const int thr  = lane & 3;

    float acc[2][4][4];
    #pragma unroll
    for (int i = 0; i < 2; i++)
        #pragma unroll
        for (int j = 0; j < 4; j++)
            #pragma unroll
            for (int r = 0; r < 4; r++) acc[i][j][r] = 0.f;

    const int KT = DN / 32;
    const int lr = tid >> 2;            // row 0..127
    const int lc = (tid & 3) * 8;       // half offset (0,8,16,24)

    // cp.async destinations; each thread does ONE A chunk + ONE B chunk
    const uint32_t awr = smem_u + (uint32_t)((lr*RS1 + lc) * 2);
    const uint32_t bwr = awr + (uint32_t)(STAGE1_H * 2);
    const __half* Arow = A + (size_t)(m0 + lr) * DN + lc;
    const __half* Wrow = W + (size_t)(n0 + lr) * DN + lc;

    // Per-lane ldmatrix base addresses (stage 0)
    const int arow  = lane & 15;
    const int koff8 = (lane >> 4) * 8;
    uint32_t aB[2], bB[2];
    #pragma unroll
    for (int i = 0; i < 2; i++)
        aB[i] = smem_u + (uint32_t)(((wm + i*16 + arow)*RS1 + koff8) * 2);
    #pragma unroll
    for (int jj = 0; jj < 2; jj++)
        bB[jj] = smem_u + (uint32_t)(STAGE1_H*2 + ((wn + jj*16 + arow)*RS1 + koff8) * 2);

    auto issue = [&](int kt) {
        const uint32_t buf = (uint32_t)(kt & 3) * STG_BYTES;
        cp16s(awr + buf, Arow + kt * 32);
        cp16s(bwr + buf, Wrow + kt * 32);
        cp_commit();
    };

    issue(0);
    issue(1);
    issue(2);

    #pragma unroll 4
    for (int kt = 0; kt < KT; ++kt) {
        if (kt + 3 < KT) asm volatile("cp.async.wait_group 2;\n");
        else             asm volatile("cp.async.wait_group 0;\n");
        __syncthreads();
        if (kt + 3 < KT) issue(kt + 3);

        const uint32_t stg = (uint32_t)((kt & 3) * STG_BYTES);

        #pragma unroll
        for (int ks = 0; ks < 2; ks++) {
            uint32_t af[2][4];
            uint32_t bfr[4][2];
            #pragma unroll
            for (int i = 0; i < 2; i++)
                ldsm4(af[i][0], af[i][1], af[i][2], af[i][3],
                      aB[i] + stg + ks*32);
            #pragma unroll
            for (int jj = 0; jj < 2; jj++) {
                uint32_t r0, r1, r2, r3;
                ldsm4(r0, r1, r2, r3, bB[jj] + stg + ks*32);
                bfr[2*jj][0]   = r0;
                bfr[2*jj+1][0] = r1;
                bfr[2*jj][1]   = r2;
                bfr[2*jj+1][1] = r3;
            }
            #pragma unroll
            for (int i = 0; i < 2; i++)
                #pragma unroll
                for (int j = 0; j < 4; j++)
                    mma_f16(&acc[i][j][0], &af[i][0], &bfr[j][0]);
        }
    }

    if (EPI == 1) {
        // Epilogue: sigmoid / log / beta_x (precise exp/log, fp16 outputs)
        const float ab = sc1[0];
        const float bscale = sc2[0];
        #pragma unroll
        for (int i = 0; i < 2; i++) {
            #pragma unroll
            for (int j = 0; j < 4; j++) {
                const int col = n0 + wn + j*8 + thr*2;
                const float b0 = __ldg(bias + col);
                const float b1 = __ldg(bias + col + 1);
                #pragma unroll
                for (int h = 0; h < 2; h++) {
                    const int row = m0 + wm + i*16 + grp + h*8;
                    const float z0 = acc[i][j][2*h+0] + b0 + ab;
                    const float z1 = acc[i][j][2*h+1] + b1 + ab;
                    const float a0 = 1.0f / (1.0f + expf(-z0));
                    const float a1 = 1.0f / (1.0f + expf(-z1));
                    const float2 xn = __half22float2(*(const __half2*)(XrefH + (size_t)row*DN + col));
                    const float la0 = logf(a0 + 1e-8f);
                    const float la1 = logf(a1 + 1e-8f);
                    const float bx0 = bscale * (1.0f - a0) * xn.x;
                    const float bx1 = bscale * (1.0f - a1) * xn.y;
                    *(__half2*)(H1 + (size_t)row*DN + col) = __floats2half2_rn(la0, la1);
                    *(__half2*)(H2 + (size_t)row*DN + col) = __floats2half2_rn(bx0, bx1);
                }
            }
        }
    } else {
        // Epilogue: z = acc * r[row] + bias; tanh.approx*0.05 + residual
        #pragma unroll
        for (int i = 0; i < 2; i++) {
            #pragma unroll
            for (int j = 0; j < 4; j++) {
                const int col = n0 + wn + j*8 + thr*2;
                const float b0 = __ldg(bias + col);
                const float b1 = __ldg(bias + col + 1);
                #pragma unroll
                for (int h = 0; h < 2; h++) {
                    const int row = m0 + wm + i*16 + grp + h*8;
                    const float r = __ldg(rowsc + row);
                    const float g0 = fast_tanh(acc[i][j][2*h+0] * r + b0);
                    const float g1 = fast_tanh(acc[i][j][2*h+1] * r + b1);
                    const float2 res = *(const float2*)(XrefF + (size_t)row*DN + col);
                    float2 o;
                    o.x = g0 * 0.05f + res.x;
                    o.y = g1 * 0.05f + res.y;
                    *(float2*)(O + (size_t)row*DN + col) = o;
                }
            }
        }
    }
}

// ---------------------------------------------------------------------------
// Scan phase 1: per (b, seg, channel-pair): segment sums (fp16 in, f32 accum)
// ---------------------------------------------------------------------------
__global__ __launch_bounds__(256) void scan_seg1(
    const __half* __restrict__ la, const __half* __restrict__ bx,
    float* __restrict__ segL, float* __restrict__ segP)
{
    const int d2 = blockIdx.x * 256 + threadIdx.x;
    const int s  = blockIdx.y;
    const int b  = blockIdx.z;
    size_t idx = (size_t)(b*TN + s*SEG) * DN + d2*2;
    float L0 = 0.f, L1 = 0.f, P0 = 0.f, P1 = 0.f;
    #pragma unroll 8
    for (int t = 0; t < SEG; t++) {
        const float2 l = __half22float2(*(const __half2*)(la + idx));
        const float2 x = __half22float2(*(const __half2*)(bx + idx));
        L0 += l.x;  L1 += l.y;
        P0 += x.x * __expf(L0);
        P1 += x.y * __expf(L1);
        idx += DN;
    }
    const size_t o = (size_t)(b*NSEG + s) * DN + d2*2;
    *(float2*)(segL + o) = make_float2(L0, L1);
    *(float2*)(segP + o) = make_float2(P0, P1);
}

// ---------------------------------------------------------------------------
// Scan phase 2: per (b, d): exclusive combine across NSEG segments.
// m = log_alpha[b, t=0, d] (cumsum non-increasing -> max at first element).
// ---------------------------------------------------------------------------
__global__ __launch_bounds__(256) void scan_seg2(
    const __half* __restrict__ la,
    const float* __restrict__ segL, const float* __restrict__ segP,
    float* __restrict__ Lb, float* __restrict__ sb)
{
    const int idx = blockIdx.x * 256 + threadIdx.x;   // 0..4095
    const int b = idx >> 10;
    const int d = idx & (DN - 1);
    const float m = __half2float(la[(size_t)b * TN * DN + d]);
    float Lex = 0.f, ss = 0.f;
    #pragma unroll
    for (int s = 0; s < NSEG; s++) {
        const size_t o = (size_t)(b*NSEG + s) * DN + d;
        Lb[o] = Lex - m;
        sb[o] = ss;
        ss  += segP[o] * __expf(Lex - m);
        Lex += segL[o];
    }
}

// ---------------------------------------------------------------------------
// Scan phase 3 FUSED with rowscale: one block per (seg, b); 512 threads cover
// all 1024 channels (half2 per thread). Per time step: compute out, block-wide
// max|out|, write fp16 out/r and rmax[row] directly (no f32 round trip).
// ---------------------------------------------------------------------------
__global__ __launch_bounds__(512) void scan_seg3f(
    const __half* __restrict__ la, const __half* __restrict__ bx,
    const float* __restrict__ Lb, const float* __restrict__ sb,
    float* __restrict__ rmax, __half* __restrict__ outh)
{
    __shared__ float red[16];
    __shared__ float bcast[2];
    const int d2   = threadIdx.x;        // 0..511 channel pair
    const int s    = blockIdx.x;
    const int b    = blockIdx.y;
    const int lane = threadIdx.x & 31;
    const int warp = threadIdx.x >> 5;   // 0..15

    const size_t o = (size_t)(b*NSEG + s) * DN + d2*2;
    const float2 Lb2 = *(const float2*)(Lb + o);
    const float2 sb2 = *(const float2*)(sb + o);
    float L0 = Lb2.x, L1 = Lb2.y;
    float s0 = sb2.x, s1 = sb2.y;
    size_t idx = (size_t)(b*TN + s*SEG) * DN + d2*2;
    const int trow = b*TN + s*SEG;

    for (int t = 0; t < SEG; t++) {
        const float2 l = __half22float2(*(const __half2*)(la + idx));
        const float2 x = __half22float2(*(const __half2*)(bx + idx));
        L0 += l.x;  L1 += l.y;
        const float c0 = __expf(L0);
        const float c1 = __expf(L1);
        s0 += x.x * c0;
        s1 += x.y * c1;
        const float o0 = s0 / (c0 + 1e-8f);
        const float o1 = s1 / (c1 + 1e-8f);

        float mx = fmaxf(fabsf(o0), fabsf(o1));
        #pragma unroll
        for (int w = 16; w > 0; w >>= 1)
            mx = fmaxf(mx, __shfl_xor_sync(0xffffffffu, mx, w));
        if (lane == 0) red[warp] = mx;
        __syncthreads();
        if (warp == 0) {
            float m2 = red[lane & 15];
            #pragma unroll
            for (int w = 8; w > 0; w >>= 1)
                m2 = fmaxf(m2, __shfl_xor_sync(0xffffffffu, m2, w));
            if (lane == 0) {
                const float r = fmaxf(m2, 1e-30f);
                bcast[t & 1] = r;
                rmax[trow + t] = r;
            }
        }
        __syncthreads();
        const float inv = 1.0f / bcast[t & 1];
        *(__half2*)(outh + idx) = __floats2half2_rn(o0 * inv, o1 * inv);
        idx += DN;
    }
}

// ---------------------------------------------------------------------------
// Launch
// ---------------------------------------------------------------------------
extern "C" void kernel_launch(void* const* d_in, const int* in_sizes, int n_in,
                              void* d_out, int out_size)
{
    const float* x    = (const float*)d_in[0];
    const float* ln_w = (const float*)d_in[1];
    const float* ln_b = (const float*)d_in[2];
    const float* Wf   = (const float*)d_in[3];
    const float* bf   = (const float*)d_in[4];
    const float* Wr   = (const float*)d_in[5];
    const float* br   = (const float*)d_in[6];
    const float* ab   = (const float*)d_in[7];
    const float* bs   = (const float*)d_in[8];
    float* out = (float*)d_out;

    float *p_rmax, *p_segL, *p_segP, *p_Lb, *p_sb;
    __half *p_xnorm, *p_la, *p_bx, *p_wf, *p_wrh, *p_scanh;
    cudaGetSymbolAddress((void**)&p_xnorm, g_xnorm);
    cudaGetSymbolAddress((void**)&p_la,    g_la);
    cudaGetSymbolAddress((void**)&p_bx,    g_bx);
    cudaGetSymbolAddress((void**)&p_scanh, g_scanh);
    cudaGetSymbolAddress((void**)&p_rmax,  g_rmax);
    cudaGetSymbolAddress((void**)&p_wf,    g_wf);
    cudaGetSymbolAddress((void**)&p_wrh,   g_wrh);
    cudaGetSymbolAddress((void**)&p_segL,  g_segL);
    cudaGetSymbolAddress((void**)&p_segP,  g_segP);
    cudaGetSymbolAddress((void**)&p_Lb,    g_Lb);
    cudaGetSymbolAddress((void**)&p_sb,    g_sb);

    cudaFuncSetAttribute(gemm_h<1>, cudaFuncAttributeMaxDynamicSharedMemorySize, GEMMH_SMEM);
    cudaFuncSetAttribute(gemm_h<2>, cudaFuncAttributeMaxDynamicSharedMemorySize, GEMMH_SMEM);

    // 0) Weight conversions (~6us total)
    cvt_h_kernel<<<(DN*DN/4)/256, 256>>>(Wf, p_wf);
    cvt_h_kernel<<<(DN*DN/4)/256, 256>>>(Wr, p_wrh);

    // 1) LayerNorm (warp-per-row, fp16 output)
    ln_kernel<<<MN/8, 256>>>(x, ln_w, ln_b, p_xnorm);

    // 2) GEMM1 (fp16, 512 thr, 32x32 warp tiles, 32 warps/SM): fused epilogue
    dim3 ggrid(DN/128, MN/128);
    gemm_h<1><<<ggrid, 512, GEMMH_SMEM>>>(
        p_xnorm, p_wf, bf, ab, bs, p_xnorm, nullptr, nullptr,
        p_la, p_bx, nullptr);

    // 3) Segmented scan over T (SEG=64, fp16 streams, f32 accumulation)
    dim3 sgrid(DN/512, NSEG, BZ);
    scan_seg1<<<sgrid, 256>>>(p_la, p_bx, p_segL, p_segP);
    scan_seg2<<<(BZ*DN)/256, 256>>>(p_la, p_segL, p_segP, p_Lb, p_sb);

    // 3b) Fused final scan + per-row scale + fp16 conversion
    scan_seg3f<<<dim3(NSEG, BZ), 512>>>(p_la, p_bx, p_Lb, p_sb, p_rmax, p_scanh);

    // 4) GEMM2 (fp16, row-rescaled): tanh(scan @ Wr^T + br)*0.05 + x
    gemm_h<2><<<ggrid, 512, GEMMH_SMEM>>>(
        p_scanh, p_wrh, br, nullptr, nullptr, nullptr, x, p_rmax,
        nullptr, nullptr, out);
}

// round 14
// speedup vs baseline: 1.1958x; 1.0099x over previous
#include <cuda_runtime.h>
#include <cuda_fp16.h>
#include <cstdint>

// Problem constants (fixed shapes)
#define BZ 4
#define TN 4096
#define DN 1024
#define MN (BZ*TN)        // 16384 rows
#define SEG 64
#define NSEG (TN/SEG)     // 64

#define NTILE_X (DN/128)          // 8
#define NTILE   ((MN/128)*NTILE_X) // 1024
#define PERSIST_CTAS 304           // 2 per SM x 152 SMs

// ---------------------------------------------------------------------------
// Scratch (static __device__ arrays; no allocation allowed)
// ---------------------------------------------------------------------------
__device__ __half g_xnorm[(size_t)MN*DN];   // fp16 LN output
__device__ __half g_la   [(size_t)MN*DN];   // fp16 log_alpha
__device__ __half g_bx   [(size_t)MN*DN];   // fp16 beta_x
__device__ __half g_scanh[(size_t)MN*DN];   // fp16 row-scaled scan output
__device__ float  g_rmax [MN];              // per-row scale
__device__ __half g_wf   [(size_t)DN*DN];   // fp16 Wf
__device__ __half g_wrh  [(size_t)DN*DN];   // fp16 Wr
__device__ float  g_segL[BZ*NSEG*DN];
__device__ float  g_segP[BZ*NSEG*DN];
__device__ float  g_Lb  [BZ*NSEG*DN];
__device__ float  g_sb  [BZ*NSEG*DN];

// ---------------------------------------------------------------------------
// Helpers
// ---------------------------------------------------------------------------
__device__ __forceinline__ void cp16s(uint32_t s, const void* g) {
    asm volatile("cp.async.cg.shared.global [%0], [%1], 16;\n" :: "r"(s), "l"(g));
}
__device__ __forceinline__ void cp_commit() {
    asm volatile("cp.async.commit_group;\n");
}
__device__ __forceinline__ void ldsm4(uint32_t& r0, uint32_t& r1, uint32_t& r2,
                                      uint32_t& r3, uint32_t addr) {
    asm volatile("ldmatrix.sync.aligned.m8n8.x4.shared.b16 {%0,%1,%2,%3}, [%4];\n"
                 : "=r"(r0), "=r"(r1), "=r"(r2), "=r"(r3) : "r"(addr));
}
__device__ __forceinline__ void mma_f16(float* c, const uint32_t* a, const uint32_t* b) {
    asm volatile(
        "mma.sync.aligned.m16n8k16.row.col.f32.f16.f16.f32 "
        "{%0,%1,%2,%3}, {%4,%5,%6,%7}, {%8,%9}, {%0,%1,%2,%3};\n"
        : "+f"(c[0]), "+f"(c[1]), "+f"(c[2]), "+f"(c[3])
        : "r"(a[0]), "r"(a[1]), "r"(a[2]), "r"(a[3]),
          "r"(b[0]), "r"(b[1]));
}
__device__ __forceinline__ float fast_tanh(float x) {
    float y; asm("tanh.approx.f32 %0, %1;" : "=f"(y) : "f"(x)); return y;
}

// ---------------------------------------------------------------------------
// Kernel 0: convert f32 weight matrix to fp16
// ---------------------------------------------------------------------------
__global__ __launch_bounds__(256) void cvt_h_kernel(
    const float* __restrict__ in, __half* __restrict__ out)
{
    const int i = blockIdx.x * 256 + threadIdx.x;
    const float4 v = ((const float4*)in)[i];
    __half2 h01 = __floats2half2_rn(v.x, v.y);
    __half2 h23 = __floats2half2_rn(v.z, v.w);
    uint2 pk;
    pk.x = *(uint32_t*)&h01;
    pk.y = *(uint32_t*)&h23;
    *(uint2*)(out + (size_t)i * 4) = pk;
}

// ---------------------------------------------------------------------------
// Kernel 1: LayerNorm, one WARP per row, fp16 output.
// ---------------------------------------------------------------------------
__global__ __launch_bounds__(256) void ln_kernel(
    const float* __restrict__ x, const float* __restrict__ w,
    const float* __restrict__ b, __half* __restrict__ y)
{
    const int warp = threadIdx.x >> 5;
    const int lane = threadIdx.x & 31;
    const int row  = blockIdx.x * 8 + warp;

    const float4* xr = (const float4*)(x + (size_t)row * DN);

    float s = 0.f;
    #pragma unroll
    for (int i = 0; i < 8; i++) {
        const float4 v = xr[lane + 32*i];
        s += (v.x + v.y) + (v.z + v.w);
    }
    #pragma unroll
    for (int o = 16; o > 0; o >>= 1) s += __shfl_xor_sync(0xffffffffu, s, o);
    const float mu = s * (1.0f / DN);

    float s2 = 0.f;
    #pragma unroll
    for (int i = 0; i < 8; i++) {
        const float4 v = xr[lane + 32*i];
        const float d0 = v.x - mu, d1 = v.y - mu, d2 = v.z - mu, d3 = v.w - mu;
        s2 += (d0*d0 + d1*d1) + (d2*d2 + d3*d3);
    }
    #pragma unroll
    for (int o = 16; o > 0; o >>= 1) s2 += __shfl_xor_sync(0xffffffffu, s2, o);
    const float rs = rsqrtf(s2 * (1.0f / DN) + 1e-5f);

    const float4* wv = (const float4*)w;
    const float4* bv = (const float4*)b;
    #pragma unroll
    for (int i = 0; i < 8; i++) {
        const int c = lane + 32*i;
        const float4 v  = xr[c];
        const float4 w4 = wv[c];
        const float4 b4 = bv[c];
        __half2 h01 = __floats2half2_rn((v.x - mu) * rs * w4.x + b4.x,
                                        (v.y - mu) * rs * w4.y + b4.y);
        __half2 h23 = __floats2half2_rn((v.z - mu) * rs * w4.z + b4.z,
                                        (v.w - mu) * rs * w4.w + b4.w);
        uint2 pk;
        pk.x = *(uint32_t*)&h01;
        pk.y = *(uint32_t*)&h23;
        *(uint2*)(y + (size_t)row * DN + c*4) = pk;
    }
}

// ---------------------------------------------------------------------------
// PERSISTENT fp16 GEMM: C[m,n] = sum_k A[m,k]*W[n,k], fp16 in, f32 accum.
// 304 resident CTAs loop over the 1024 (128x128) tiles -> no tail wave.
// 512 threads (16 warps, 32x32 warp tile), BK=32, 4-stage cp.async ring,
// ldmatrix fragments, 2 CTAs/SM.
// EPI==1: sigmoid/log_alpha/beta_x epilogue (fp16 out).
// EPI==2: per-row-rescale + tanh*0.05 + residual (f32 out).
// ---------------------------------------------------------------------------
#define RS1 40                       // smem row stride in halves (80B)
#define STAGE1_H (128*RS1)           // halves per operand per stage
#define STG_BYTES (2*STAGE1_H*2)     // A+B bytes per stage = 20480
#define NST 4
#define GEMMH_SMEM (NST*STG_BYTES)   // 81920 (2 CTAs/SM)

template<int EPI>
__global__ __launch_bounds__(512, 2) void gemm_h(
    const __half* __restrict__ A, const __half* __restrict__ W,
    const float* __restrict__ bias,
    const float* __restrict__ sc1,    // alpha_bias (EPI==1)
    const float* __restrict__ sc2,    // beta_scale (EPI==1)
    const __half* __restrict__ XrefH, // x_norm fp16 (EPI==1)
    const float* __restrict__ XrefF,  // residual x (EPI==2)
    const float* __restrict__ rowsc,  // per-row scale (EPI==2)
    __half* __restrict__ H1,          // log_alpha (EPI==1)
    __half* __restrict__ H2,          // beta_x (EPI==1)
    float*  __restrict__ O)           // final out (EPI==2)
{
    extern __shared__ char dynsm[];
    const uint32_t smem_u = (uint32_t)__cvta_generic_to_shared(dynsm);

    const int tid  = threadIdx.x;
    const int lane = tid & 31;
    const int warp = tid >> 5;             // 0..15
    const int wm   = (warp & 3) * 32;      // 4 m-strips of 32
    const int wn   = (warp >> 2) * 32;     // 4 n-strips of 32
    const int grp  = lane >> 2;
    const int thr  = lane & 3;

    const int KT = DN / 32;
    const int lr = tid >> 2;            // row 0..127
    const int lc = (tid & 3) * 8;       // half offset (0,8,16,24)

    // cp.async destinations; each thread does ONE A chunk + ONE B chunk
    const uint32_t awr = smem_u + (uint32_t)((lr*RS1 + lc) * 2);
    const uint32_t bwr = awr + (uint32_t)(STAGE1_H * 2);

    // Per-lane ldmatrix base addresses (stage 0)
    const int arow  = lane & 15;
    const int koff8 = (lane >> 4) * 8;
    uint32_t aB[2], bB[2];
    #pragma unroll
    for (int i = 0; i < 2; i++)
        aB[i] = smem_u + (uint32_t)(((wm + i*16 + arow)*RS1 + koff8) * 2);
    #pragma unroll
    for (int jj = 0; jj < 2; jj++)
        bB[jj] = smem_u + (uint32_t)(STAGE1_H*2 + ((wn + jj*16 + arow)*RS1 + koff8) * 2);

    for (int tile = blockIdx.x; tile < NTILE; tile += PERSIST_CTAS) {
        const int m0 = (tile >> 3) * 128;       // tile / NTILE_X
        const int n0 = (tile & 7) * 128;        // tile % NTILE_X

        const __half* Arow = A + (size_t)(m0 + lr) * DN + lc;
        const __half* Wrow = W + (size_t)(n0 + lr) * DN + lc;

        float acc[2][4][4];
        #pragma unroll
        for (int i = 0; i < 2; i++)
            #pragma unroll
            for (int j = 0; j < 4; j++)
                #pragma unroll
                for (int r = 0; r < 4; r++) acc[i][j][r] = 0.f;

        // Protect smem ring reuse across tiles: all warps must finish ldsm
        // of the previous tile before new cp.async writes land.
        __syncthreads();

        auto issue = [&](int kt) {
            const uint32_t buf = (uint32_t)(kt & 3) * STG_BYTES;
            cp16s(awr + buf, Arow + kt * 32);
            cp16s(bwr + buf, Wrow + kt * 32);
            cp_commit();
        };

        issue(0);
        issue(1);
        issue(2);

        #pragma unroll 4
        for (int kt = 0; kt < KT; ++kt) {
            if (kt + 3 < KT) asm volatile("cp.async.wait_group 2;\n");
            else             asm volatile("cp.async.wait_group 0;\n");
            __syncthreads();
            if (kt + 3 < KT) issue(kt + 3);

            const uint32_t stg = (uint32_t)((kt & 3) * STG_BYTES);

            #pragma unroll
            for (int ks = 0; ks < 2; ks++) {
                uint32_t af[2][4];
                uint32_t bfr[4][2];
                #pragma unroll
                for (int i = 0; i < 2; i++)
                    ldsm4(af[i][0], af[i][1], af[i][2], af[i][3],
                          aB[i] + stg + ks*32);
                #pragma unroll
                for (int jj = 0; jj < 2; jj++) {
                    uint32_t r0, r1, r2, r3;
                    ldsm4(r0, r1, r2, r3, bB[jj] + stg + ks*32);
                    bfr[2*jj][0]   = r0;
                    bfr[2*jj+1][0] = r1;
                    bfr[2*jj][1]   = r2;
                    bfr[2*jj+1][1] = r3;
                }
                #pragma unroll
                for (int i = 0; i < 2; i++)
                    #pragma unroll
                    for (int j = 0; j < 4; j++)
                        mma_f16(&acc[i][j][0], &af[i][0], &bfr[j][0]);
            }
        }

        if (EPI == 1) {
            // Epilogue: sigmoid / log / beta_x (precise exp/log, fp16 outputs)
            const float ab = sc1[0];
            const float bscale = sc2[0];
            #pragma unroll
            for (int i = 0; i < 2; i++) {
                #pragma unroll
                for (int j = 0; j < 4; j++) {
                    const int col = n0 + wn + j*8 + thr*2;
                    const float b0 = __ldg(bias + col);
                    const float b1 = __ldg(bias + col + 1);
                    #pragma unroll
                    for (int h = 0; h < 2; h++) {
                        const int row = m0 + wm + i*16 + grp + h*8;
                        const float z0 = acc[i][j][2*h+0] + b0 + ab;
                        const float z1 = acc[i][j][2*h+1] + b1 + ab;
                        const float a0 = 1.0f / (1.0f + expf(-z0));
                        const float a1 = 1.0f / (1.0f + expf(-z1));
                        const float2 xn = __half22float2(*(const __half2*)(XrefH + (size_t)row*DN + col));
                        const float la0 = logf(a0 + 1e-8f);
                        const float la1 = logf(a1 + 1e-8f);
                        const float bx0 = bscale * (1.0f - a0) * xn.x;
                        const float bx1 = bscale * (1.0f - a1) * xn.y;
                        *(__half2*)(H1 + (size_t)row*DN + col) = __floats2half2_rn(la0, la1);
                        *(__half2*)(H2 + (size_t)row*DN + col) = __floats2half2_rn(bx0, bx1);
                    }
                }
            }
        } else {
            // Epilogue: z = acc * r[row] + bias; tanh.approx*0.05 + residual
            #pragma unroll
            for (int i = 0; i < 2; i++) {
                #pragma unroll
                for (int j = 0; j < 4; j++) {
                    const int col = n0 + wn + j*8 + thr*2;
                    const float b0 = __ldg(bias + col);
                    const float b1 = __ldg(bias + col + 1);
                    #pragma unroll
                    for (int h = 0; h < 2; h++) {
                        const int row = m0 + wm + i*16 + grp + h*8;
                        const float r = __ldg(rowsc + row);
                        const float g0 = fast_tanh(acc[i][j][2*h+0] * r + b0);
                        const float g1 = fast_tanh(acc[i][j][2*h+1] * r + b1);
                        const float2 res = *(const float2*)(XrefF + (size_t)row*DN + col);
                        float2 o;
                        o.x = g0 * 0.05f + res.x;
                        o.y = g1 * 0.05f + res.y;
                        *(float2*)(O + (size_t)row*DN + col) = o;
                    }
                }
            }
        }
    }
}

// ---------------------------------------------------------------------------
// Scan phase 1: per (b, seg, channel-pair): segment sums (fp16 in, f32 accum)
// ---------------------------------------------------------------------------
__global__ __launch_bounds__(256) void scan_seg1(
    const __half* __restrict__ la, const __half* __restrict__ bx,
    float* __restrict__ segL, float* __restrict__ segP)
{
    const int d2 = blockIdx.x * 256 + threadIdx.x;
    const int s  = blockIdx.y;
    const int b  = blockIdx.z;
    size_t idx = (size_t)(b*TN + s*SEG) * DN + d2*2;
    float L0 = 0.f, L1 = 0.f, P0 = 0.f, P1 = 0.f;
    #pragma unroll 8
    for (int t = 0; t < SEG; t++) {
        const float2 l = __half22float2(*(const __half2*)(la + idx));
        const float2 x = __half22float2(*(const __half2*)(bx + idx));
        L0 += l.x;  L1 += l.y;
        P0 += x.x * __expf(L0);
        P1 += x.y * __expf(L1);
        idx += DN;
    }
    const size_t o = (size_t)(b*NSEG + s) * DN + d2*2;
    *(float2*)(segL + o) = make_float2(L0, L1);
    *(float2*)(segP + o) = make_float2(P0, P1);
}

// ---------------------------------------------------------------------------
// Scan phase 2: per (b, d): exclusive combine across NSEG segments.
// m = log_alpha[b, t=0, d] (cumsum non-increasing -> max at first element).
// ---------------------------------------------------------------------------
__global__ __launch_bounds__(256) void scan_seg2(
    const __half* __restrict__ la,
    const float* __restrict__ segL, const float* __restrict__ segP,
    float* __restrict__ Lb, float* __restrict__ sb)
{
    const int idx = blockIdx.x * 256 + threadIdx.x;   // 0..4095
    const int b = idx >> 10;
    const int d = idx & (DN - 1);
    const float m = __half2float(la[(size_t)b * TN * DN + d]);
    float Lex = 0.f, ss = 0.f;
    #pragma unroll
    for (int s = 0; s < NSEG; s++) {
        const size_t o = (size_t)(b*NSEG + s) * DN + d;
        Lb[o] = Lex - m;
        sb[o] = ss;
        ss  += segP[o] * __expf(Lex - m);
        Lex += segL[o];
    }
}

// ---------------------------------------------------------------------------
// Scan phase 3 FUSED with rowscale: one block per (seg, b); 512 threads cover
// all 1024 channels (half2 per thread). Per time step: compute out, block-wide
// max|out|, write fp16 out/r and rmax[row] directly (no f32 round trip).
// ---------------------------------------------------------------------------
__global__ __launch_bounds__(512) void scan_seg3f(
    const __half* __restrict__ la, const __half* __restrict__ bx,
    const float* __restrict__ Lb, const float* __restrict__ sb,
    float* __restrict__ rmax, __half* __restrict__ outh)
{
    __shared__ float red[16];
    __shared__ float bcast[2];
    const int d2   = threadIdx.x;        // 0..511 channel pair
    const int s    = blockIdx.x;
    const int b    = blockIdx.y;
    const int lane = threadIdx.x & 31;
    const int warp = threadIdx.x >> 5;   // 0..15

    const size_t o = (size_t)(b*NSEG + s) * DN + d2*2;
    const float2 Lb2 = *(const float2*)(Lb + o);
    const float2 sb2 = *(const float2*)(sb + o);
    float L0 = Lb2.x, L1 = Lb2.y;
    float s0 = sb2.x, s1 = sb2.y;
    size_t idx = (size_t)(b*TN + s*SEG) * DN + d2*2;
    const int trow = b*TN + s*SEG;

    for (int t = 0; t < SEG; t++) {
        const float2 l = __half22float2(*(const __half2*)(la + idx));
        const float2 x = __half22float2(*(const __half2*)(bx + idx));
        L0 += l.x;  L1 += l.y;
        const float c0 = __expf(L0);
        const float c1 = __expf(L1);
        s0 += x.x * c0;
        s1 += x.y * c1;
        const float o0 = s0 / (c0 + 1e-8f);
        const float o1 = s1 / (c1 + 1e-8f);

        float mx = fmaxf(fabsf(o0), fabsf(o1));
        #pragma unroll
        for (int w = 16; w > 0; w >>= 1)
            mx = fmaxf(mx, __shfl_xor_sync(0xffffffffu, mx, w));
        if (lane == 0) red[warp] = mx;
        __syncthreads();
        if (warp == 0) {
            float m2 = red[lane & 15];
            #pragma unroll
            for (int w = 8; w > 0; w >>= 1)
                m2 = fmaxf(m2, __shfl_xor_sync(0xffffffffu, m2, w));
            if (lane == 0) {
                const float r = fmaxf(m2, 1e-30f);
                bcast[t & 1] = r;
                rmax[trow + t] = r;
            }
        }
        __syncthreads();
        const float inv = 1.0f / bcast[t & 1];
        *(__half2*)(outh + idx) = __floats2half2_rn(o0 * inv, o1 * inv);
        idx += DN;
    }
}

// ---------------------------------------------------------------------------
// Launch
// ---------------------------------------------------------------------------
extern "C" void kernel_launch(void* const* d_in, const int* in_sizes, int n_in,
                              void* d_out, int out_size)
{
    const float* x    = (const float*)d_in[0];
    const float* ln_w = (const float*)d_in[1];
    const float* ln_b = (const float*)d_in[2];
    const float* Wf   = (const float*)d_in[3];
    const float* bf   = (const float*)d_in[4];
    const float* Wr   = (const float*)d_in[5];
    const float* br   = (const float*)d_in[6];
    const float* ab   = (const float*)d_in[7];
    const float* bs   = (const float*)d_in[8];
    float* out = (float*)d_out;

    float *p_rmax, *p_segL, *p_segP, *p_Lb, *p_sb;
    __half *p_xnorm, *p_la, *p_bx, *p_wf, *p_wrh, *p_scanh;
    cudaGetSymbolAddress((void**)&p_xnorm, g_xnorm);
    cudaGetSymbolAddress((void**)&p_la,    g_la);
    cudaGetSymbolAddress((void**)&p_bx,    g_bx);
    cudaGetSymbolAddress((void**)&p_scanh, g_scanh);
    cudaGetSymbolAddress((void**)&p_rmax,  g_rmax);
    cudaGetSymbolAddress((void**)&p_wf,    g_wf);
    cudaGetSymbolAddress((void**)&p_wrh,   g_wrh);
    cudaGetSymbolAddress((void**)&p_segL,  g_segL);
    cudaGetSymbolAddress((void**)&p_segP,  g_segP);
    cudaGetSymbolAddress((void**)&p_Lb,    g_Lb);
    cudaGetSymbolAddress((void**)&p_sb,    g_sb);

    cudaFuncSetAttribute(gemm_h<1>, cudaFuncAttributeMaxDynamicSharedMemorySize, GEMMH_SMEM);
    cudaFuncSetAttribute(gemm_h<2>, cudaFuncAttributeMaxDynamicSharedMemorySize, GEMMH_SMEM);

    // 0) Weight conversions (~6us total)
    cvt_h_kernel<<<(DN*DN/4)/256, 256>>>(Wf, p_wf);
    cvt_h_kernel<<<(DN*DN/4)/256, 256>>>(Wr, p_wrh);

    // 1) LayerNorm (warp-per-row, fp16 output)
    ln_kernel<<<MN/8, 256>>>(x, ln_w, ln_b, p_xnorm);

    // 2) GEMM1 (persistent, fp16, 512 thr, 32x32 warp tiles): fused epilogue
    gemm_h<1><<<PERSIST_CTAS, 512, GEMMH_SMEM>>>(
        p_xnorm, p_wf, bf, ab, bs, p_xnorm, nullptr, nullptr,
        p_la, p_bx, nullptr);

    // 3) Segmented scan over T (SEG=64, fp16 streams, f32 accumulation)
    dim3 sgrid(DN/512, NSEG, BZ);
    scan_seg1<<<sgrid, 256>>>(p_la, p_bx, p_segL, p_segP);
    scan_seg2<<<(BZ*DN)/256, 256>>>(p_la, p_segL, p_segP, p_Lb, p_sb);

    // 3b) Fused final scan + per-row scale + fp16 conversion
    scan_seg3f<<<dim3(NSEG, BZ), 512>>>(p_la, p_bx, p_Lb, p_sb, p_rmax, p_scanh);

    // 4) GEMM2 (persistent, fp16, row-rescaled): tanh(scan @ Wr^T)*0.05 + x
    gemm_h<2><<<PERSIST_CTAS, 512, GEMMH_SMEM>>>(
        p_scanh, p_wrh, br, nullptr, nullptr, nullptr, x, p_rmax,
        nullptr, nullptr, out);
}